// round 13
// baseline (speedup 1.0000x reference)
#include <cuda_runtime.h>
#include <cuda_fp16.h>
#include <math.h>
#include <stdint.h>

#define B_ 4
#define T_ 4096
#define C_ 1024
#define H_ 64
#define IPB 80                       // sum over 32 qtiles of (qq/8+1)
#define NIT (B_*IPB)                 // 320

__device__ __half g_q[B_*T_*H_];     // [b][t][h], 1/32 folded
__device__ __half g_k[B_*T_*H_];
__device__ __half g_v[B_*H_*T_];     // transposed [b][h][t]
__device__ __half g_pacc[(size_t)NIT*128*64];   // fp16 partial O
__device__ float g_pm[NIT*128], g_pl[NIT*128];

__device__ __forceinline__ uint32_t su32(const void* p){ return (uint32_t)__cvta_generic_to_shared(p); }
__device__ __forceinline__ void ldsm4(uint32_t a, uint32_t& r0, uint32_t& r1, uint32_t& r2, uint32_t& r3){
    asm volatile("ldmatrix.sync.aligned.m8n8.x4.shared.b16 {%0,%1,%2,%3}, [%4];"
                 : "=r"(r0),"=r"(r1),"=r"(r2),"=r"(r3) : "r"(a));
}
__device__ __forceinline__ void ldsm4t(uint32_t a, uint32_t& r0, uint32_t& r1, uint32_t& r2, uint32_t& r3){
    asm volatile("ldmatrix.sync.aligned.m8n8.x4.trans.shared.b16 {%0,%1,%2,%3}, [%4];"
                 : "=r"(r0),"=r"(r1),"=r"(r2),"=r"(r3) : "r"(a));
}
__device__ __forceinline__ void mmaf16(float* d, const uint32_t* a, uint32_t b0, uint32_t b1){
    asm volatile("mma.sync.aligned.m16n8k16.row.col.f32.f16.f16.f32 "
                 "{%0,%1,%2,%3}, {%4,%5,%6,%7}, {%8,%9}, {%0,%1,%2,%3};"
                 : "+f"(d[0]),"+f"(d[1]),"+f"(d[2]),"+f"(d[3])
                 : "r"(a[0]),"r"(a[1]),"r"(a[2]),"r"(a[3]),"r"(b0),"r"(b1));
}
__device__ __forceinline__ uint32_t packh2(float x, float y){
    __half2 h = __float22half2_rn(make_float2(x,y));
    return *(uint32_t*)&h;
}
__device__ __forceinline__ void cpa16(uint32_t dst, const void* src){
    asm volatile("cp.async.cg.shared.global [%0], [%1], 16;"::"r"(dst),"l"(src));
}
__device__ __forceinline__ void cpcommit(){ asm volatile("cp.async.commit_group;"); }
template<int N> __device__ __forceinline__ void cpwait(){
    asm volatile("cp.async.wait_group %0;"::"n"(N));
}

// ------------- Kernel 1: fused QKV, M=128 tile, 512 threads (R12 proven) ----
#define XS 40
#define XTS (128*XS)
#define XSW 200
#define WTS (32*XSW)
__global__ void __launch_bounds__(512,1)
qkv_kernel(const float* __restrict__ x, const float* __restrict__ Wq,
           const float* __restrict__ Wk, const float* __restrict__ Wv){
    __shared__ __half xs[2][XTS], ws[2][WTS];
    const int tid=threadIdx.x, lane=tid&31, w=tid>>5;
    const int wm=w>>2, wn=w&3;
    const int row0=blockIdx.x*128;

    float acc[2][6][4];
#pragma unroll
    for(int a=0;a<2;a++)
#pragma unroll
        for(int b=0;b<6;b++)
#pragma unroll
            for(int i=0;i<4;i++) acc[a][b][i]=0.f;

    const int ra_=(lane&15), ca_=(lane>>4)*8;
    const int rbt=((lane>>3)&1)*8+(lane&7), cbt=(lane>>4)*8;
    const int xr0=tid>>3, xc0=(tid&7)<<2;
    int wr[3], wn4[3]; const float* wsrc[3]; float wsc[3];
#pragma unroll
    for(int i=0;i<3;i++){
        int idx=tid+i*512;
        wr[i]=idx/48; wn4[i]=(idx%48)<<2;
        int mat=wn4[i]>>6;
        wsrc[i]= mat==0?Wq:(mat==1?Wk:Wv);
        wsc[i] = mat==0?0.03125f:1.f;
    }

    float4 xv[2], wv[3];
    xv[0]=*(const float4*)(x+(size_t)(row0+xr0)*C_+xc0);
    xv[1]=*(const float4*)(x+(size_t)(row0+xr0+64)*C_+xc0);
#pragma unroll
    for(int i=0;i<3;i++)
        wv[i]=*(const float4*)(wsrc[i]+(size_t)wr[i]*H_+(wn4[i]&63));

    for(int k0=0, it=0; k0<C_; k0+=32, it++){
        const int cur=it&1;
        const bool more=(k0+32<C_);
#pragma unroll
        for(int i=0;i<2;i++){
            int r=xr0+i*64;
            *(uint2*)&xs[cur][r*XS+xc0]=make_uint2(packh2(xv[i].x,xv[i].y),
                                                   packh2(xv[i].z,xv[i].w));
        }
#pragma unroll
        for(int i=0;i<3;i++){
            float s=wsc[i];
            *(uint2*)&ws[cur][wr[i]*XSW+wn4[i]]=
                make_uint2(packh2(wv[i].x*s,wv[i].y*s),packh2(wv[i].z*s,wv[i].w*s));
        }
        if(more){
            xv[0]=*(const float4*)(x+(size_t)(row0+xr0)*C_+k0+32+xc0);
            xv[1]=*(const float4*)(x+(size_t)(row0+xr0+64)*C_+k0+32+xc0);
#pragma unroll
            for(int i=0;i<3;i++)
                wv[i]=*(const float4*)(wsrc[i]+(size_t)(k0+32+wr[i])*H_+(wn4[i]&63));
        }
        __syncthreads();

#pragma unroll
        for(int ks=0;ks<32;ks+=16){
            uint32_t a[2][4];
#pragma unroll
            for(int mf=0;mf<2;mf++){
                int rr=wm*32+mf*16+ra_, cc=ks+ca_;
                ldsm4(su32(&xs[cur][rr*XS+cc]),a[mf][0],a[mf][1],a[mf][2],a[mf][3]);
            }
#pragma unroll
            for(int p=0;p<3;p++){
                int n0=wn*48+p*16;
                uint32_t b[4];
                ldsm4t(su32(&ws[cur][(ks+rbt)*XSW+n0+cbt]),b[0],b[1],b[2],b[3]);
#pragma unroll
                for(int mf=0;mf<2;mf++){
                    mmaf16(acc[mf][p*2],  a[mf],b[0],b[1]);
                    mmaf16(acc[mf][p*2+1],a[mf],b[2],b[3]);
                }
            }
        }
        __syncthreads();
    }
#pragma unroll
    for(int mf=0;mf<2;mf++){
        int r0=row0+wm*32+mf*16+(lane>>2), r1=r0+8;
#pragma unroll
        for(int nf=0;nf<6;nf++){
            int n=wn*48+nf*8+(lane&3)*2, mat=n>>6, h=n&63;
            float* d=acc[mf][nf];
            if(mat<2){
                __half* dst = mat? g_k : g_q;
                *(uint32_t*)(dst+(size_t)r0*H_+h)=packh2(d[0],d[1]);
                *(uint32_t*)(dst+(size_t)r1*H_+h)=packh2(d[2],d[3]);
            } else {
                int b0=r0>>12, t0=r0&4095, b1=r1>>12, t1=r1&4095;
                size_t o0=((size_t)b0*H_+h)*T_+t0, o1=((size_t)b1*H_+h)*T_+t1;
                g_v[o0]=__float2half(d[0]); g_v[o0+T_]=__float2half(d[1]);
                g_v[o1]=__float2half(d[2]); g_v[o1+T_]=__float2half(d[3]);
            }
        }
    }
}

// ------------- Kernel 2: fp16 flash attention (seg=16, fp16 partials) -------
#define KS 72
#define STG (64*KS)
__global__ void __launch_bounds__(128)
attn_kernel(float* __restrict__ out){
    __shared__ __half ks[2][STG], vs[2][STG];
    const int tid=threadIdx.x, lane=tid&31, w=tid>>5;
    int id=(int)gridDim.x-1-blockIdx.x;              // heavy first
    int b=id/IPB, r=id%IPB, qq=0;
    for(;;){ int c=(qq>>3)+1; if(r<c) break; r-=c; qq++; }
    const int seg=r, nsegs=(qq>>3)+1;
    const int j0=seg*16, j1=min(j0+16, 2*qq+2);
    const int qrb=qq*128 + w*32 + (lane>>2);

    const __half *qp=g_q+(size_t)b*T_*H_;
    const __half *kp=g_k+(size_t)b*T_*H_;
    const __half *vp=g_v+(size_t)b*H_*T_;
    const int lr=tid>>3, lc=(tid&7)<<3;

#pragma unroll
    for(int i=0;i<4;i++){
        int rr=lr+i*16;
        cpa16(su32(&ks[0][rr*KS+lc]), kp+(size_t)(j0*64+rr)*H_+lc);
        cpa16(su32(&vs[0][rr*KS+lc]), vp+(size_t)rr*T_+j0*64+lc);
    }
    cpcommit();

    uint32_t qa[2][4][4];
#pragma unroll
    for(int mf=0;mf<2;mf++)
#pragma unroll
        for(int s=0;s<4;s++){
            int c0=s*16+(lane&3)*2;
            size_t o0=(size_t)(qrb+mf*16)*H_, o1=(size_t)(qrb+mf*16+8)*H_;
            qa[mf][s][0]=*(const uint32_t*)(qp+o0+c0);
            qa[mf][s][1]=*(const uint32_t*)(qp+o1+c0);
            qa[mf][s][2]=*(const uint32_t*)(qp+o0+c0+8);
            qa[mf][s][3]=*(const uint32_t*)(qp+o1+c0+8);
        }

    float o[2][8][4];
#pragma unroll
    for(int mf=0;mf<2;mf++)
#pragma unroll
        for(int f=0;f<8;f++){o[mf][f][0]=0.f;o[mf][f][1]=0.f;o[mf][f][2]=0.f;o[mf][f][3]=0.f;}
    float m[2][2], l[2][2];
#pragma unroll
    for(int mf=0;mf<2;mf++){m[mf][0]=-INFINITY;m[mf][1]=-INFINITY;l[mf][0]=0.f;l[mf][1]=0.f;}
    const int rb=(lane>>4)*8+(lane&7), cb=((lane>>3)&1)*8;

    for(int j=j0;j<j1;j++){
        const int cur=(j-j0)&1;
        if(j+1<j1){
            const int nx=cur^1;
#pragma unroll
            for(int i=0;i<4;i++){
                int rr=lr+i*16;
                cpa16(su32(&ks[nx][rr*KS+lc]), kp+(size_t)((j+1)*64+rr)*H_+lc);
                cpa16(su32(&vs[nx][rr*KS+lc]), vp+(size_t)rr*T_+(j+1)*64+lc);
            }
            cpcommit(); cpwait<1>();
        } else cpwait<0>();
        __syncthreads();

        float sa[2][8][4];
#pragma unroll
        for(int mf=0;mf<2;mf++)
#pragma unroll
            for(int f=0;f<8;f++){sa[mf][f][0]=0.f;sa[mf][f][1]=0.f;sa[mf][f][2]=0.f;sa[mf][f][3]=0.f;}
#pragma unroll
        for(int s=0;s<4;s++)
#pragma unroll
            for(int p=0;p<4;p++){
                uint32_t bb[4];
                ldsm4(su32(&ks[cur][(p*16+rb)*KS+s*16+cb]),bb[0],bb[1],bb[2],bb[3]);
#pragma unroll
                for(int mf=0;mf<2;mf++){
                    mmaf16(sa[mf][p*2],  qa[mf][s],bb[0],bb[1]);
                    mmaf16(sa[mf][p*2+1],qa[mf][s],bb[2],bb[3]);
                }
            }

        if(j>=2*qq){
#pragma unroll
            for(int mf=0;mf<2;mf++){
                int q0=qrb+mf*16, q1=q0+8;
#pragma unroll
                for(int f=0;f<8;f++){
                    int kg=j*64+f*8+(lane&3)*2;
                    if(kg  >q0) sa[mf][f][0]=-INFINITY;
                    if(kg+1>q0) sa[mf][f][1]=-INFINITY;
                    if(kg  >q1) sa[mf][f][2]=-INFINITY;
                    if(kg+1>q1) sa[mf][f][3]=-INFINITY;
                }
            }
        }

        uint32_t ph[2][4][4];
#pragma unroll
        for(int mf=0;mf<2;mf++){
            float mt0=-INFINITY,mt1=-INFINITY;
#pragma unroll
            for(int f=0;f<8;f++){
                mt0=fmaxf(mt0,fmaxf(sa[mf][f][0],sa[mf][f][1]));
                mt1=fmaxf(mt1,fmaxf(sa[mf][f][2],sa[mf][f][3]));
            }
            mt0=fmaxf(mt0,__shfl_xor_sync(~0u,mt0,1)); mt0=fmaxf(mt0,__shfl_xor_sync(~0u,mt0,2));
            mt1=fmaxf(mt1,__shfl_xor_sync(~0u,mt1,1)); mt1=fmaxf(mt1,__shfl_xor_sync(~0u,mt1,2));
            float mn0=fmaxf(m[mf][0],mt0), mn1=fmaxf(m[mf][1],mt1);
            float a0=__expf(m[mf][0]-mn0), a1=__expf(m[mf][1]-mn1);
            float s0=0.f,s1=0.f;
#pragma unroll
            for(int f=0;f<8;f++){
                sa[mf][f][0]=__expf(sa[mf][f][0]-mn0); s0+=sa[mf][f][0];
                sa[mf][f][1]=__expf(sa[mf][f][1]-mn0); s0+=sa[mf][f][1];
                sa[mf][f][2]=__expf(sa[mf][f][2]-mn1); s1+=sa[mf][f][2];
                sa[mf][f][3]=__expf(sa[mf][f][3]-mn1); s1+=sa[mf][f][3];
            }
            s0+=__shfl_xor_sync(~0u,s0,1); s0+=__shfl_xor_sync(~0u,s0,2);
            s1+=__shfl_xor_sync(~0u,s1,1); s1+=__shfl_xor_sync(~0u,s1,2);
            l[mf][0]=l[mf][0]*a0+s0; l[mf][1]=l[mf][1]*a1+s1;
            m[mf][0]=mn0; m[mf][1]=mn1;
#pragma unroll
            for(int f=0;f<8;f++){
                o[mf][f][0]*=a0; o[mf][f][1]*=a0; o[mf][f][2]*=a1; o[mf][f][3]*=a1;
            }
#pragma unroll
            for(int s=0;s<4;s++){
                ph[mf][s][0]=packh2(sa[mf][2*s][0],  sa[mf][2*s][1]);
                ph[mf][s][1]=packh2(sa[mf][2*s][2],  sa[mf][2*s][3]);
                ph[mf][s][2]=packh2(sa[mf][2*s+1][0],sa[mf][2*s+1][1]);
                ph[mf][s][3]=packh2(sa[mf][2*s+1][2],sa[mf][2*s+1][3]);
            }
        }

#pragma unroll
        for(int s=0;s<4;s++)
#pragma unroll
            for(int p=0;p<4;p++){
                uint32_t bb[4];
                ldsm4(su32(&vs[cur][(p*16+rb)*KS+s*16+cb]),bb[0],bb[1],bb[2],bb[3]);
#pragma unroll
                for(int mf=0;mf<2;mf++){
                    mmaf16(o[mf][p*2],  ph[mf][s],bb[0],bb[1]);
                    mmaf16(o[mf][p*2+1],ph[mf][s],bb[2],bb[3]);
                }
            }
        __syncthreads();
    }

    if(nsegs==1){
#pragma unroll
        for(int mf=0;mf<2;mf++){
            int r0=qrb+mf*16, r1=r0+8;
            float i0=1.f/l[mf][0], i1=1.f/l[mf][1];
            size_t ob0=((size_t)b*T_+r0)*H_, ob1=((size_t)b*T_+r1)*H_;
#pragma unroll
            for(int f=0;f<8;f++){
                int h=f*8+(lane&3)*2;
                *(float2*)(out+ob0+h)=make_float2(o[mf][f][0]*i0,o[mf][f][1]*i0);
                *(float2*)(out+ob1+h)=make_float2(o[mf][f][2]*i1,o[mf][f][3]*i1);
            }
        }
    } else {
        __half* pp=g_pacc+(size_t)id*8192;
#pragma unroll
        for(int mf=0;mf<2;mf++){
            int rl0=w*32+mf*16+(lane>>2), rl1=rl0+8;
#pragma unroll
            for(int f=0;f<8;f++){
                int h=f*8+(lane&3)*2;
                *(uint32_t*)(pp+rl0*64+h)=packh2(o[mf][f][0],o[mf][f][1]);
                *(uint32_t*)(pp+rl1*64+h)=packh2(o[mf][f][2],o[mf][f][3]);
            }
            if((lane&3)==0){
                g_pm[id*128+rl0]=m[mf][0]; g_pl[id*128+rl0]=l[mf][0];
                g_pm[id*128+rl1]=m[mf][1]; g_pl[id*128+rl1]=l[mf][1];
            }
        }
    }
}

// ------------- Kernel 3: combine fp16 partials (qq>=8), high-MLP ------------
__global__ void __launch_bounds__(512)
comb_kernel(float* __restrict__ out){
    const int qq=blockIdx.x+8, b=blockIdx.y;
    const int g=qq>>3, rr=qq&7;
    const int base=b*IPB+(g+1)*(4*g+rr), nseg=g+1;
    const int ql=threadIdx.x>>2, hg=(threadIdx.x&3)*16;   // row, 16-col chunk

    float mstar=-INFINITY;
#pragma unroll 4
    for(int s=0;s<nseg;s++) mstar=fmaxf(mstar,g_pm[(base+s)*128+ql]);
    float wgt[4], lsum=0.f;
#pragma unroll 4
    for(int s=0;s<nseg;s++){
        wgt[s]=__expf(g_pm[(base+s)*128+ql]-mstar);
        lsum+=g_pl[(base+s)*128+ql]*wgt[s];
    }
    // batched loads: up to 4 segs x 2 uint4 in flight
    uint4 dat[4][2];
#pragma unroll 4
    for(int s=0;s<nseg;s++){
        const uint4* p=(const uint4*)(g_pacc+((size_t)(base+s)*8192+ql*64+hg));
        dat[s][0]=p[0]; dat[s][1]=p[1];
    }
    float acc[16];
#pragma unroll
    for(int i=0;i<16;i++) acc[i]=0.f;
#pragma unroll 4
    for(int s=0;s<nseg;s++){
        float wg=wgt[s];
#pragma unroll
        for(int h=0;h<2;h++){
            const uint32_t* u=(const uint32_t*)&dat[s][h];
#pragma unroll
            for(int i=0;i<4;i++){
                float2 v=__half22float2(*(const __half2*)&u[i]);
                acc[h*8+2*i]  +=wg*v.x;
                acc[h*8+2*i+1]+=wg*v.y;
            }
        }
    }
    float inv=1.f/lsum;
    float4* po=(float4*)(out+((size_t)b*T_+qq*128+ql)*H_+hg);
#pragma unroll
    for(int i=0;i<4;i++)
        po[i]=make_float4(acc[4*i]*inv,acc[4*i+1]*inv,acc[4*i+2]*inv,acc[4*i+3]*inv);
}

extern "C" void kernel_launch(void* const* d_in, const int* in_sizes, int n_in,
                              void* d_out, int out_size){
    qkv_kernel<<<(B_*T_)/128,512>>>((const float*)d_in[0],(const float*)d_in[1],
                                    (const float*)d_in[2],(const float*)d_in[3]);
    attn_kernel<<<NIT,128>>>((float*)d_out);
    comb_kernel<<<dim3(24,4),512>>>((float*)d_out);
}

// round 14
// speedup vs baseline: 1.0184x; 1.0184x over previous
#include <cuda_runtime.h>
#include <cuda_fp16.h>
#include <math.h>
#include <stdint.h>

#define B_ 4
#define T_ 4096
#define C_ 1024
#define H_ 64
#define IPB 80                       // sum over 32 qtiles of (qq/8+1)
#define NIT (B_*IPB)                 // 320

__device__ __half g_q[B_*T_*H_];     // [b][t][h], 1/32 folded
__device__ __half g_k[B_*T_*H_];
__device__ __half g_v[B_*H_*T_];     // transposed [b][h][t]
__device__ __half g_w[C_*192];       // fp16 W in [k][n] (q|k|v), 1/32 folded in q
__device__ float g_pacc[(size_t)NIT*128*64];
__device__ float g_pm[NIT*128], g_pl[NIT*128];

__device__ __forceinline__ uint32_t su32(const void* p){ return (uint32_t)__cvta_generic_to_shared(p); }
__device__ __forceinline__ void ldsm4(uint32_t a, uint32_t& r0, uint32_t& r1, uint32_t& r2, uint32_t& r3){
    asm volatile("ldmatrix.sync.aligned.m8n8.x4.shared.b16 {%0,%1,%2,%3}, [%4];"
                 : "=r"(r0),"=r"(r1),"=r"(r2),"=r"(r3) : "r"(a));
}
__device__ __forceinline__ void ldsm4t(uint32_t a, uint32_t& r0, uint32_t& r1, uint32_t& r2, uint32_t& r3){
    asm volatile("ldmatrix.sync.aligned.m8n8.x4.trans.shared.b16 {%0,%1,%2,%3}, [%4];"
                 : "=r"(r0),"=r"(r1),"=r"(r2),"=r"(r3) : "r"(a));
}
__device__ __forceinline__ void mmaf16(float* d, const uint32_t* a, uint32_t b0, uint32_t b1){
    asm volatile("mma.sync.aligned.m16n8k16.row.col.f32.f16.f16.f32 "
                 "{%0,%1,%2,%3}, {%4,%5,%6,%7}, {%8,%9}, {%0,%1,%2,%3};"
                 : "+f"(d[0]),"+f"(d[1]),"+f"(d[2]),"+f"(d[3])
                 : "r"(a[0]),"r"(a[1]),"r"(a[2]),"r"(a[3]),"r"(b0),"r"(b1));
}
__device__ __forceinline__ uint32_t packh2(float x, float y){
    __half2 h = __float22half2_rn(make_float2(x,y));
    return *(uint32_t*)&h;
}
__device__ __forceinline__ void cpa16(uint32_t dst, const void* src){
    asm volatile("cp.async.cg.shared.global [%0], [%1], 16;"::"r"(dst),"l"(src));
}
__device__ __forceinline__ void cpcommit(){ asm volatile("cp.async.commit_group;"); }
template<int N> __device__ __forceinline__ void cpwait(){
    asm volatile("cp.async.wait_group %0;"::"n"(N));
}

// ------------- Kernel 0: streaming convert W fp32->fp16, [k][n] layout ------
// 128 CTAs x 128 thr = 16384 threads; thread = (k, 4 h-cols) per matrix.
__global__ void __launch_bounds__(128)
prep_w(const float* __restrict__ Wq, const float* __restrict__ Wk,
       const float* __restrict__ Wv){
    const int t=blockIdx.x*128+threadIdx.x;
    const int k=t>>4, h4=(t&15)<<2;
    float4 q =*(const float4*)(Wq+(size_t)k*H_+h4);
    float4 kk=*(const float4*)(Wk+(size_t)k*H_+h4);
    float4 vv=*(const float4*)(Wv+(size_t)k*H_+h4);
    __half* d=g_w+(size_t)k*192;
    *(uint2*)(d+h4)    =make_uint2(packh2(q.x*0.03125f,q.y*0.03125f),
                                   packh2(q.z*0.03125f,q.w*0.03125f));
    *(uint2*)(d+64+h4) =make_uint2(packh2(kk.x,kk.y),packh2(kk.z,kk.w));
    *(uint2*)(d+128+h4)=make_uint2(packh2(vv.x,vv.y),packh2(vv.z,vv.w));
}

// ------------- Kernel 1: fused QKV, M=128, 512 thr, W via cp.async ----------
#define XS 40
#define XTS (128*XS)
#define XSW 200
#define WTS (32*XSW)
__global__ void __launch_bounds__(512,1)
qkv_kernel(const float* __restrict__ x){
    __shared__ __half xs[2][XTS], ws[2][WTS];
    const int tid=threadIdx.x, lane=tid&31, w=tid>>5;
    const int wm=w>>2, wn=w&3;
    const int row0=blockIdx.x*128;

    float acc[2][6][4];
#pragma unroll
    for(int a=0;a<2;a++)
#pragma unroll
        for(int b=0;b<6;b++)
#pragma unroll
            for(int i=0;i<4;i++) acc[a][b][i]=0.f;

    const int ra_=(lane&15), ca_=(lane>>4)*8;
    const int rbt=((lane>>3)&1)*8+(lane&7), cbt=(lane>>4)*8;
    const int xr0=tid>>3, xc0=(tid&7)<<2;
    // W cp.async: 768 x 16B chunks per 32-k chunk; 1.5/thread
    const int wi0=tid, wi1=512+ (tid&255);       // threads 0..255 take second
    const int wr0=wi0/24, wc0=(wi0%24)<<3;
    const int wr1=wi1/24, wc1=(wi1%24)<<3;
    const bool wdo1=(tid<256);

    float4 xv[2];
    xv[0]=*(const float4*)(x+(size_t)(row0+xr0)*C_+xc0);
    xv[1]=*(const float4*)(x+(size_t)(row0+xr0+64)*C_+xc0);
    cpa16(su32(&ws[0][wr0*XSW+wc0]), g_w+(size_t)wr0*192+wc0);
    if(wdo1) cpa16(su32(&ws[0][wr1*XSW+wc1]), g_w+(size_t)wr1*192+wc1);
    cpcommit();

    for(int k0=0, it=0; k0<C_; k0+=32, it++){
        const int cur=it&1;
        const bool more=(k0+32<C_);
        if(more){
            cpa16(su32(&ws[cur^1][wr0*XSW+wc0]), g_w+(size_t)(k0+32+wr0)*192+wc0);
            if(wdo1) cpa16(su32(&ws[cur^1][wr1*XSW+wc1]), g_w+(size_t)(k0+32+wr1)*192+wc1);
            cpcommit();
        }
#pragma unroll
        for(int i=0;i<2;i++){
            int r=xr0+i*64;
            *(uint2*)&xs[cur][r*XS+xc0]=make_uint2(packh2(xv[i].x,xv[i].y),
                                                   packh2(xv[i].z,xv[i].w));
        }
        if(more){
            xv[0]=*(const float4*)(x+(size_t)(row0+xr0)*C_+k0+32+xc0);
            xv[1]=*(const float4*)(x+(size_t)(row0+xr0+64)*C_+k0+32+xc0);
        }
        if(more) cpwait<1>(); else cpwait<0>();
        __syncthreads();

#pragma unroll
        for(int ks=0;ks<32;ks+=16){
            uint32_t a[2][4];
#pragma unroll
            for(int mf=0;mf<2;mf++){
                int rr=wm*32+mf*16+ra_, cc=ks+ca_;
                ldsm4(su32(&xs[cur][rr*XS+cc]),a[mf][0],a[mf][1],a[mf][2],a[mf][3]);
            }
#pragma unroll
            for(int p=0;p<3;p++){
                int n0=wn*48+p*16;
                uint32_t b[4];
                ldsm4t(su32(&ws[cur][(ks+rbt)*XSW+n0+cbt]),b[0],b[1],b[2],b[3]);
#pragma unroll
                for(int mf=0;mf<2;mf++){
                    mmaf16(acc[mf][p*2],  a[mf],b[0],b[1]);
                    mmaf16(acc[mf][p*2+1],a[mf],b[2],b[3]);
                }
            }
        }
        __syncthreads();
    }
#pragma unroll
    for(int mf=0;mf<2;mf++){
        int r0=row0+wm*32+mf*16+(lane>>2), r1=r0+8;
#pragma unroll
        for(int nf=0;nf<6;nf++){
            int n=wn*48+nf*8+(lane&3)*2, mat=n>>6, h=n&63;
            float* d=acc[mf][nf];
            if(mat<2){
                __half* dst = mat? g_k : g_q;
                *(uint32_t*)(dst+(size_t)r0*H_+h)=packh2(d[0],d[1]);
                *(uint32_t*)(dst+(size_t)r1*H_+h)=packh2(d[2],d[3]);
            } else {
                int b0=r0>>12, t0=r0&4095, b1=r1>>12, t1=r1&4095;
                size_t o0=((size_t)b0*H_+h)*T_+t0, o1=((size_t)b1*H_+h)*T_+t1;
                g_v[o0]=__float2half(d[0]); g_v[o0+T_]=__float2half(d[1]);
                g_v[o1]=__float2half(d[2]); g_v[o1+T_]=__float2half(d[3]);
            }
        }
    }
}

// ------------- Kernel 2: fp16 flash attention (R12 proven, seg=16) ----------
#define KS 72
#define STG (64*KS)
__global__ void __launch_bounds__(128)
attn_kernel(float* __restrict__ out){
    __shared__ __half ks[2][STG], vs[2][STG];
    const int tid=threadIdx.x, lane=tid&31, w=tid>>5;
    int id=(int)gridDim.x-1-blockIdx.x;              // heavy first
    int b=id/IPB, r=id%IPB, qq=0;
    for(;;){ int c=(qq>>3)+1; if(r<c) break; r-=c; qq++; }
    const int seg=r, nsegs=(qq>>3)+1;
    const int j0=seg*16, j1=min(j0+16, 2*qq+2);
    const int qrb=qq*128 + w*32 + (lane>>2);

    const __half *qp=g_q+(size_t)b*T_*H_;
    const __half *kp=g_k+(size_t)b*T_*H_;
    const __half *vp=g_v+(size_t)b*H_*T_;
    const int lr=tid>>3, lc=(tid&7)<<3;

#pragma unroll
    for(int i=0;i<4;i++){
        int rr=lr+i*16;
        cpa16(su32(&ks[0][rr*KS+lc]), kp+(size_t)(j0*64+rr)*H_+lc);
        cpa16(su32(&vs[0][rr*KS+lc]), vp+(size_t)rr*T_+j0*64+lc);
    }
    cpcommit();

    uint32_t qa[2][4][4];
#pragma unroll
    for(int mf=0;mf<2;mf++)
#pragma unroll
        for(int s=0;s<4;s++){
            int c0=s*16+(lane&3)*2;
            size_t o0=(size_t)(qrb+mf*16)*H_, o1=(size_t)(qrb+mf*16+8)*H_;
            qa[mf][s][0]=*(const uint32_t*)(qp+o0+c0);
            qa[mf][s][1]=*(const uint32_t*)(qp+o1+c0);
            qa[mf][s][2]=*(const uint32_t*)(qp+o0+c0+8);
            qa[mf][s][3]=*(const uint32_t*)(qp+o1+c0+8);
        }

    float o[2][8][4];
#pragma unroll
    for(int mf=0;mf<2;mf++)
#pragma unroll
        for(int f=0;f<8;f++){o[mf][f][0]=0.f;o[mf][f][1]=0.f;o[mf][f][2]=0.f;o[mf][f][3]=0.f;}
    float m[2][2], l[2][2];
#pragma unroll
    for(int mf=0;mf<2;mf++){m[mf][0]=-INFINITY;m[mf][1]=-INFINITY;l[mf][0]=0.f;l[mf][1]=0.f;}
    const int rb=(lane>>4)*8+(lane&7), cb=((lane>>3)&1)*8;

    for(int j=j0;j<j1;j++){
        const int cur=(j-j0)&1;
        if(j+1<j1){
            const int nx=cur^1;
#pragma unroll
            for(int i=0;i<4;i++){
                int rr=lr+i*16;
                cpa16(su32(&ks[nx][rr*KS+lc]), kp+(size_t)((j+1)*64+rr)*H_+lc);
                cpa16(su32(&vs[nx][rr*KS+lc]), vp+(size_t)rr*T_+(j+1)*64+lc);
            }
            cpcommit(); cpwait<1>();
        } else cpwait<0>();
        __syncthreads();

        float sa[2][8][4];
#pragma unroll
        for(int mf=0;mf<2;mf++)
#pragma unroll
            for(int f=0;f<8;f++){sa[mf][f][0]=0.f;sa[mf][f][1]=0.f;sa[mf][f][2]=0.f;sa[mf][f][3]=0.f;}
#pragma unroll
        for(int s=0;s<4;s++)
#pragma unroll
            for(int p=0;p<4;p++){
                uint32_t bb[4];
                ldsm4(su32(&ks[cur][(p*16+rb)*KS+s*16+cb]),bb[0],bb[1],bb[2],bb[3]);
#pragma unroll
                for(int mf=0;mf<2;mf++){
                    mmaf16(sa[mf][p*2],  qa[mf][s],bb[0],bb[1]);
                    mmaf16(sa[mf][p*2+1],qa[mf][s],bb[2],bb[3]);
                }
            }

        if(j>=2*qq){
#pragma unroll
            for(int mf=0;mf<2;mf++){
                int q0=qrb+mf*16, q1=q0+8;
#pragma unroll
                for(int f=0;f<8;f++){
                    int kg=j*64+f*8+(lane&3)*2;
                    if(kg  >q0) sa[mf][f][0]=-INFINITY;
                    if(kg+1>q0) sa[mf][f][1]=-INFINITY;
                    if(kg  >q1) sa[mf][f][2]=-INFINITY;
                    if(kg+1>q1) sa[mf][f][3]=-INFINITY;
                }
            }
        }

        uint32_t ph[2][4][4];
#pragma unroll
        for(int mf=0;mf<2;mf++){
            float mt0=-INFINITY,mt1=-INFINITY;
#pragma unroll
            for(int f=0;f<8;f++){
                mt0=fmaxf(mt0,fmaxf(sa[mf][f][0],sa[mf][f][1]));
                mt1=fmaxf(mt1,fmaxf(sa[mf][f][2],sa[mf][f][3]));
            }
            mt0=fmaxf(mt0,__shfl_xor_sync(~0u,mt0,1)); mt0=fmaxf(mt0,__shfl_xor_sync(~0u,mt0,2));
            mt1=fmaxf(mt1,__shfl_xor_sync(~0u,mt1,1)); mt1=fmaxf(mt1,__shfl_xor_sync(~0u,mt1,2));
            float mn0=fmaxf(m[mf][0],mt0), mn1=fmaxf(m[mf][1],mt1);
            float a0=__expf(m[mf][0]-mn0), a1=__expf(m[mf][1]-mn1);
            float s0=0.f,s1=0.f;
#pragma unroll
            for(int f=0;f<8;f++){
                sa[mf][f][0]=__expf(sa[mf][f][0]-mn0); s0+=sa[mf][f][0];
                sa[mf][f][1]=__expf(sa[mf][f][1]-mn0); s0+=sa[mf][f][1];
                sa[mf][f][2]=__expf(sa[mf][f][2]-mn1); s1+=sa[mf][f][2];
                sa[mf][f][3]=__expf(sa[mf][f][3]-mn1); s1+=sa[mf][f][3];
            }
            s0+=__shfl_xor_sync(~0u,s0,1); s0+=__shfl_xor_sync(~0u,s0,2);
            s1+=__shfl_xor_sync(~0u,s1,1); s1+=__shfl_xor_sync(~0u,s1,2);
            l[mf][0]=l[mf][0]*a0+s0; l[mf][1]=l[mf][1]*a1+s1;
            m[mf][0]=mn0; m[mf][1]=mn1;
#pragma unroll
            for(int f=0;f<8;f++){
                o[mf][f][0]*=a0; o[mf][f][1]*=a0; o[mf][f][2]*=a1; o[mf][f][3]*=a1;
            }
#pragma unroll
            for(int s=0;s<4;s++){
                ph[mf][s][0]=packh2(sa[mf][2*s][0],  sa[mf][2*s][1]);
                ph[mf][s][1]=packh2(sa[mf][2*s][2],  sa[mf][2*s][3]);
                ph[mf][s][2]=packh2(sa[mf][2*s+1][0],sa[mf][2*s+1][1]);
                ph[mf][s][3]=packh2(sa[mf][2*s+1][2],sa[mf][2*s+1][3]);
            }
        }

#pragma unroll
        for(int s=0;s<4;s++)
#pragma unroll
            for(int p=0;p<4;p++){
                uint32_t bb[4];
                ldsm4(su32(&vs[cur][(p*16+rb)*KS+s*16+cb]),bb[0],bb[1],bb[2],bb[3]);
#pragma unroll
                for(int mf=0;mf<2;mf++){
                    mmaf16(o[mf][p*2],  ph[mf][s],bb[0],bb[1]);
                    mmaf16(o[mf][p*2+1],ph[mf][s],bb[2],bb[3]);
                }
            }
        __syncthreads();
    }

    if(nsegs==1){
#pragma unroll
        for(int mf=0;mf<2;mf++){
            int r0=qrb+mf*16, r1=r0+8;
            float i0=1.f/l[mf][0], i1=1.f/l[mf][1];
            size_t ob0=((size_t)b*T_+r0)*H_, ob1=((size_t)b*T_+r1)*H_;
#pragma unroll
            for(int f=0;f<8;f++){
                int h=f*8+(lane&3)*2;
                *(float2*)(out+ob0+h)=make_float2(o[mf][f][0]*i0,o[mf][f][1]*i0);
                *(float2*)(out+ob1+h)=make_float2(o[mf][f][2]*i1,o[mf][f][3]*i1);
            }
        }
    } else {
        float* pp=g_pacc+(size_t)id*8192;
#pragma unroll
        for(int mf=0;mf<2;mf++){
            int rl0=w*32+mf*16+(lane>>2), rl1=rl0+8;
#pragma unroll
            for(int f=0;f<8;f++){
                int h=f*8+(lane&3)*2;
                *(float2*)(pp+rl0*64+h)=make_float2(o[mf][f][0],o[mf][f][1]);
                *(float2*)(pp+rl1*64+h)=make_float2(o[mf][f][2],o[mf][f][3]);
            }
            if((lane&3)==0){
                g_pm[id*128+rl0]=m[mf][0]; g_pl[id*128+rl0]=l[mf][0];
                g_pm[id*128+rl1]=m[mf][1]; g_pl[id*128+rl1]=l[mf][1];
            }
        }
    }
}

// ------------- Kernel 3: combine partials (qq>=8 only, R12 proven) ----------
__global__ void __launch_bounds__(512)
comb_kernel(float* __restrict__ out){
    const int qq=blockIdx.x+8, b=blockIdx.y;
    const int g=qq>>3, rr=qq&7;
    const int base=b*IPB+(g+1)*(4*g+rr), nseg=g+1;
    const int ql=threadIdx.x>>2, hg=(threadIdx.x&3)*16;

    float mstar=-INFINITY;
    for(int s=0;s<nseg;s++) mstar=fmaxf(mstar,g_pm[(base+s)*128+ql]);
    float lsum=0.f, acc[16];
#pragma unroll
    for(int i=0;i<16;i++) acc[i]=0.f;
    for(int s=0;s<nseg;s++){
        float wgt=__expf(g_pm[(base+s)*128+ql]-mstar);
        lsum+=g_pl[(base+s)*128+ql]*wgt;
        const float4* p=(const float4*)(g_pacc+((size_t)(base+s)*8192+ql*64+hg));
#pragma unroll
        for(int i=0;i<4;i++){
            float4 v=p[i];
            acc[4*i]  +=wgt*v.x; acc[4*i+1]+=wgt*v.y;
            acc[4*i+2]+=wgt*v.z; acc[4*i+3]+=wgt*v.w;
        }
    }
    float inv=1.f/lsum;
    float4* po=(float4*)(out+((size_t)b*T_+qq*128+ql)*H_+hg);
#pragma unroll
    for(int i=0;i<4;i++)
        po[i]=make_float4(acc[4*i]*inv,acc[4*i+1]*inv,acc[4*i+2]*inv,acc[4*i+3]*inv);
}

extern "C" void kernel_launch(void* const* d_in, const int* in_sizes, int n_in,
                              void* d_out, int out_size){
    prep_w<<<128,128>>>((const float*)d_in[1],(const float*)d_in[2],(const float*)d_in[3]);
    qkv_kernel<<<(B_*T_)/128,512>>>((const float*)d_in[0]);
    attn_kernel<<<NIT,128>>>((float*)d_out);
    comb_kernel<<<dim3(24,4),512>>>((float*)d_out);
}

// round 15
// speedup vs baseline: 1.0230x; 1.0045x over previous
#include <cuda_runtime.h>
#include <cuda_fp16.h>
#include <math.h>
#include <stdint.h>

#define B_ 4
#define T_ 4096
#define C_ 1024
#define H_ 64
#define IPB 80                       // sum over 32 qtiles of (qq/8+1)
#define NIT (B_*IPB)                 // 320

__device__ __half g_q[B_*T_*H_];     // [b][t][h], 1/32 folded
__device__ __half g_k[B_*T_*H_];
__device__ __half g_v[B_*H_*T_];     // transposed [b][h][t]
__device__ __half g_w[C_*192];       // fp16 W in [k][n] (q|k|v), 1/32 folded in q
__device__ float g_pacc[(size_t)NIT*128*64];
__device__ float g_pm[NIT*128], g_pl[NIT*128];

__device__ __forceinline__ uint32_t su32(const void* p){ return (uint32_t)__cvta_generic_to_shared(p); }
__device__ __forceinline__ void ldsm4(uint32_t a, uint32_t& r0, uint32_t& r1, uint32_t& r2, uint32_t& r3){
    asm volatile("ldmatrix.sync.aligned.m8n8.x4.shared.b16 {%0,%1,%2,%3}, [%4];"
                 : "=r"(r0),"=r"(r1),"=r"(r2),"=r"(r3) : "r"(a));
}
__device__ __forceinline__ void ldsm4t(uint32_t a, uint32_t& r0, uint32_t& r1, uint32_t& r2, uint32_t& r3){
    asm volatile("ldmatrix.sync.aligned.m8n8.x4.trans.shared.b16 {%0,%1,%2,%3}, [%4];"
                 : "=r"(r0),"=r"(r1),"=r"(r2),"=r"(r3) : "r"(a));
}
__device__ __forceinline__ void mmaf16(float* d, const uint32_t* a, uint32_t b0, uint32_t b1){
    asm volatile("mma.sync.aligned.m16n8k16.row.col.f32.f16.f16.f32 "
                 "{%0,%1,%2,%3}, {%4,%5,%6,%7}, {%8,%9}, {%0,%1,%2,%3};"
                 : "+f"(d[0]),"+f"(d[1]),"+f"(d[2]),"+f"(d[3])
                 : "r"(a[0]),"r"(a[1]),"r"(a[2]),"r"(a[3]),"r"(b0),"r"(b1));
}
__device__ __forceinline__ uint32_t packh2(float x, float y){
    __half2 h = __float22half2_rn(make_float2(x,y));
    return *(uint32_t*)&h;
}
__device__ __forceinline__ void cpa16(uint32_t dst, const void* src){
    asm volatile("cp.async.cg.shared.global [%0], [%1], 16;"::"r"(dst),"l"(src));
}
__device__ __forceinline__ void cpcommit(){ asm volatile("cp.async.commit_group;"); }
template<int N> __device__ __forceinline__ void cpwait(){
    asm volatile("cp.async.wait_group %0;"::"n"(N));
}

// ------------- Kernel 0: streaming convert W fp32->fp16, [k][n] layout ------
__global__ void __launch_bounds__(128)
prep_w(const float* __restrict__ Wq, const float* __restrict__ Wk,
       const float* __restrict__ Wv){
    const int t=blockIdx.x*128+threadIdx.x;
    const int k=t>>4, h4=(t&15)<<2;
    float4 q =*(const float4*)(Wq+(size_t)k*H_+h4);
    float4 kk=*(const float4*)(Wk+(size_t)k*H_+h4);
    float4 vv=*(const float4*)(Wv+(size_t)k*H_+h4);
    __half* d=g_w+(size_t)k*192;
    *(uint2*)(d+h4)    =make_uint2(packh2(q.x*0.03125f,q.y*0.03125f),
                                   packh2(q.z*0.03125f,q.w*0.03125f));
    *(uint2*)(d+64+h4) =make_uint2(packh2(kk.x,kk.y),packh2(kk.z,kk.w));
    *(uint2*)(d+128+h4)=make_uint2(packh2(vv.x,vv.y),packh2(vv.z,vv.w));
}

// ------------- Kernel 1: fused QKV, M=128, 512 thr, W via cp.async ----------
#define XS 40
#define XTS (128*XS)
#define XSW 200
#define WTS (32*XSW)
__global__ void __launch_bounds__(512,1)
qkv_kernel(const float* __restrict__ x){
    __shared__ __half xs[2][XTS], ws[2][WTS];
    const int tid=threadIdx.x, lane=tid&31, w=tid>>5;
    const int wm=w>>2, wn=w&3;
    const int row0=blockIdx.x*128;

    float acc[2][6][4];
#pragma unroll
    for(int a=0;a<2;a++)
#pragma unroll
        for(int b=0;b<6;b++)
#pragma unroll
            for(int i=0;i<4;i++) acc[a][b][i]=0.f;

    const int ra_=(lane&15), ca_=(lane>>4)*8;
    const int rbt=((lane>>3)&1)*8+(lane&7), cbt=(lane>>4)*8;
    const int xr0=tid>>3, xc0=(tid&7)<<2;
    const int wi0=tid, wi1=512+(tid&255);
    const int wr0=wi0/24, wc0=(wi0%24)<<3;
    const int wr1=wi1/24, wc1=(wi1%24)<<3;
    const bool wdo1=(tid<256);

    float4 xv[2];
    xv[0]=*(const float4*)(x+(size_t)(row0+xr0)*C_+xc0);
    xv[1]=*(const float4*)(x+(size_t)(row0+xr0+64)*C_+xc0);
    cpa16(su32(&ws[0][wr0*XSW+wc0]), g_w+(size_t)wr0*192+wc0);
    if(wdo1) cpa16(su32(&ws[0][wr1*XSW+wc1]), g_w+(size_t)wr1*192+wc1);
    cpcommit();

    for(int k0=0, it=0; k0<C_; k0+=32, it++){
        const int cur=it&1;
        const bool more=(k0+32<C_);
        if(more){
            cpa16(su32(&ws[cur^1][wr0*XSW+wc0]), g_w+(size_t)(k0+32+wr0)*192+wc0);
            if(wdo1) cpa16(su32(&ws[cur^1][wr1*XSW+wc1]), g_w+(size_t)(k0+32+wr1)*192+wc1);
            cpcommit();
        }
#pragma unroll
        for(int i=0;i<2;i++){
            int r=xr0+i*64;
            *(uint2*)&xs[cur][r*XS+xc0]=make_uint2(packh2(xv[i].x,xv[i].y),
                                                   packh2(xv[i].z,xv[i].w));
        }
        if(more){
            xv[0]=*(const float4*)(x+(size_t)(row0+xr0)*C_+k0+32+xc0);
            xv[1]=*(const float4*)(x+(size_t)(row0+xr0+64)*C_+k0+32+xc0);
        }
        if(more) cpwait<1>(); else cpwait<0>();
        __syncthreads();

#pragma unroll
        for(int ks=0;ks<32;ks+=16){
            uint32_t a[2][4];
#pragma unroll
            for(int mf=0;mf<2;mf++){
                int rr=wm*32+mf*16+ra_, cc=ks+ca_;
                ldsm4(su32(&xs[cur][rr*XS+cc]),a[mf][0],a[mf][1],a[mf][2],a[mf][3]);
            }
#pragma unroll
            for(int p=0;p<3;p++){
                int n0=wn*48+p*16;
                uint32_t b[4];
                ldsm4t(su32(&ws[cur][(ks+rbt)*XSW+n0+cbt]),b[0],b[1],b[2],b[3]);
#pragma unroll
                for(int mf=0;mf<2;mf++){
                    mmaf16(acc[mf][p*2],  a[mf],b[0],b[1]);
                    mmaf16(acc[mf][p*2+1],a[mf],b[2],b[3]);
                }
            }
        }
        __syncthreads();
    }
#pragma unroll
    for(int mf=0;mf<2;mf++){
        int r0=row0+wm*32+mf*16+(lane>>2), r1=r0+8;
#pragma unroll
        for(int nf=0;nf<6;nf++){
            int n=wn*48+nf*8+(lane&3)*2, mat=n>>6, h=n&63;
            float* d=acc[mf][nf];
            if(mat<2){
                __half* dst = mat? g_k : g_q;
                *(uint32_t*)(dst+(size_t)r0*H_+h)=packh2(d[0],d[1]);
                *(uint32_t*)(dst+(size_t)r1*H_+h)=packh2(d[2],d[3]);
            } else {
                int b0=r0>>12, t0=r0&4095, b1=r1>>12, t1=r1&4095;
                size_t o0=((size_t)b0*H_+h)*T_+t0, o1=((size_t)b1*H_+h)*T_+t1;
                g_v[o0]=__float2half(d[0]); g_v[o0+T_]=__float2half(d[1]);
                g_v[o1]=__float2half(d[2]); g_v[o1+T_]=__float2half(d[3]);
            }
        }
    }
}

// ------------- Kernel 2: fp16 flash attention (R12 proven, seg=16) ----------
#define KS 72
#define STG (64*KS)
__global__ void __launch_bounds__(128)
attn_kernel(float* __restrict__ out){
    __shared__ __half ks[2][STG], vs[2][STG];
    const int tid=threadIdx.x, lane=tid&31, w=tid>>5;
    int id=(int)gridDim.x-1-blockIdx.x;              // heavy first
    int b=id/IPB, r=id%IPB, qq=0;
    for(;;){ int c=(qq>>3)+1; if(r<c) break; r-=c; qq++; }
    const int seg=r, nsegs=(qq>>3)+1;
    const int j0=seg*16, j1=min(j0+16, 2*qq+2);
    const int qrb=qq*128 + w*32 + (lane>>2);

    const __half *qp=g_q+(size_t)b*T_*H_;
    const __half *kp=g_k+(size_t)b*T_*H_;
    const __half *vp=g_v+(size_t)b*H_*T_;
    const int lr=tid>>3, lc=(tid&7)<<3;

#pragma unroll
    for(int i=0;i<4;i++){
        int rr=lr+i*16;
        cpa16(su32(&ks[0][rr*KS+lc]), kp+(size_t)(j0*64+rr)*H_+lc);
        cpa16(su32(&vs[0][rr*KS+lc]), vp+(size_t)rr*T_+j0*64+lc);
    }
    cpcommit();

    uint32_t qa[2][4][4];
#pragma unroll
    for(int mf=0;mf<2;mf++)
#pragma unroll
        for(int s=0;s<4;s++){
            int c0=s*16+(lane&3)*2;
            size_t o0=(size_t)(qrb+mf*16)*H_, o1=(size_t)(qrb+mf*16+8)*H_;
            qa[mf][s][0]=*(const uint32_t*)(qp+o0+c0);
            qa[mf][s][1]=*(const uint32_t*)(qp+o1+c0);
            qa[mf][s][2]=*(const uint32_t*)(qp+o0+c0+8);
            qa[mf][s][3]=*(const uint32_t*)(qp+o1+c0+8);
        }

    float o[2][8][4];
#pragma unroll
    for(int mf=0;mf<2;mf++)
#pragma unroll
        for(int f=0;f<8;f++){o[mf][f][0]=0.f;o[mf][f][1]=0.f;o[mf][f][2]=0.f;o[mf][f][3]=0.f;}
    float m[2][2], l[2][2];
#pragma unroll
    for(int mf=0;mf<2;mf++){m[mf][0]=-INFINITY;m[mf][1]=-INFINITY;l[mf][0]=0.f;l[mf][1]=0.f;}
    const int rb=(lane>>4)*8+(lane&7), cb=((lane>>3)&1)*8;

    for(int j=j0;j<j1;j++){
        const int cur=(j-j0)&1;
        if(j+1<j1){
            const int nx=cur^1;
#pragma unroll
            for(int i=0;i<4;i++){
                int rr=lr+i*16;
                cpa16(su32(&ks[nx][rr*KS+lc]), kp+(size_t)((j+1)*64+rr)*H_+lc);
                cpa16(su32(&vs[nx][rr*KS+lc]), vp+(size_t)rr*T_+(j+1)*64+lc);
            }
            cpcommit(); cpwait<1>();
        } else cpwait<0>();
        __syncthreads();

        float sa[2][8][4];
#pragma unroll
        for(int mf=0;mf<2;mf++)
#pragma unroll
            for(int f=0;f<8;f++){sa[mf][f][0]=0.f;sa[mf][f][1]=0.f;sa[mf][f][2]=0.f;sa[mf][f][3]=0.f;}
#pragma unroll
        for(int s=0;s<4;s++)
#pragma unroll
            for(int p=0;p<4;p++){
                uint32_t bb[4];
                ldsm4(su32(&ks[cur][(p*16+rb)*KS+s*16+cb]),bb[0],bb[1],bb[2],bb[3]);
#pragma unroll
                for(int mf=0;mf<2;mf++){
                    mmaf16(sa[mf][p*2],  qa[mf][s],bb[0],bb[1]);
                    mmaf16(sa[mf][p*2+1],qa[mf][s],bb[2],bb[3]);
                }
            }

        if(j>=2*qq){
#pragma unroll
            for(int mf=0;mf<2;mf++){
                int q0=qrb+mf*16, q1=q0+8;
#pragma unroll
                for(int f=0;f<8;f++){
                    int kg=j*64+f*8+(lane&3)*2;
                    if(kg  >q0) sa[mf][f][0]=-INFINITY;
                    if(kg+1>q0) sa[mf][f][1]=-INFINITY;
                    if(kg  >q1) sa[mf][f][2]=-INFINITY;
                    if(kg+1>q1) sa[mf][f][3]=-INFINITY;
                }
            }
        }

        uint32_t ph[2][4][4];
#pragma unroll
        for(int mf=0;mf<2;mf++){
            float mt0=-INFINITY,mt1=-INFINITY;
#pragma unroll
            for(int f=0;f<8;f++){
                mt0=fmaxf(mt0,fmaxf(sa[mf][f][0],sa[mf][f][1]));
                mt1=fmaxf(mt1,fmaxf(sa[mf][f][2],sa[mf][f][3]));
            }
            mt0=fmaxf(mt0,__shfl_xor_sync(~0u,mt0,1)); mt0=fmaxf(mt0,__shfl_xor_sync(~0u,mt0,2));
            mt1=fmaxf(mt1,__shfl_xor_sync(~0u,mt1,1)); mt1=fmaxf(mt1,__shfl_xor_sync(~0u,mt1,2));
            float mn0=fmaxf(m[mf][0],mt0), mn1=fmaxf(m[mf][1],mt1);
            float a0=__expf(m[mf][0]-mn0), a1=__expf(m[mf][1]-mn1);
            float s0=0.f,s1=0.f;
#pragma unroll
            for(int f=0;f<8;f++){
                sa[mf][f][0]=__expf(sa[mf][f][0]-mn0); s0+=sa[mf][f][0];
                sa[mf][f][1]=__expf(sa[mf][f][1]-mn0); s0+=sa[mf][f][1];
                sa[mf][f][2]=__expf(sa[mf][f][2]-mn1); s1+=sa[mf][f][2];
                sa[mf][f][3]=__expf(sa[mf][f][3]-mn1); s1+=sa[mf][f][3];
            }
            s0+=__shfl_xor_sync(~0u,s0,1); s0+=__shfl_xor_sync(~0u,s0,2);
            s1+=__shfl_xor_sync(~0u,s1,1); s1+=__shfl_xor_sync(~0u,s1,2);
            l[mf][0]=l[mf][0]*a0+s0; l[mf][1]=l[mf][1]*a1+s1;
            m[mf][0]=mn0; m[mf][1]=mn1;
#pragma unroll
            for(int f=0;f<8;f++){
                o[mf][f][0]*=a0; o[mf][f][1]*=a0; o[mf][f][2]*=a1; o[mf][f][3]*=a1;
            }
#pragma unroll
            for(int s=0;s<4;s++){
                ph[mf][s][0]=packh2(sa[mf][2*s][0],  sa[mf][2*s][1]);
                ph[mf][s][1]=packh2(sa[mf][2*s][2],  sa[mf][2*s][3]);
                ph[mf][s][2]=packh2(sa[mf][2*s+1][0],sa[mf][2*s+1][1]);
                ph[mf][s][3]=packh2(sa[mf][2*s+1][2],sa[mf][2*s+1][3]);
            }
        }

#pragma unroll
        for(int s=0;s<4;s++)
#pragma unroll
            for(int p=0;p<4;p++){
                uint32_t bb[4];
                ldsm4(su32(&vs[cur][(p*16+rb)*KS+s*16+cb]),bb[0],bb[1],bb[2],bb[3]);
#pragma unroll
                for(int mf=0;mf<2;mf++){
                    mmaf16(o[mf][p*2],  ph[mf][s],bb[0],bb[1]);
                    mmaf16(o[mf][p*2+1],ph[mf][s],bb[2],bb[3]);
                }
            }
        __syncthreads();
    }

    if(nsegs==1){
#pragma unroll
        for(int mf=0;mf<2;mf++){
            int r0=qrb+mf*16, r1=r0+8;
            float i0=1.f/l[mf][0], i1=1.f/l[mf][1];
            size_t ob0=((size_t)b*T_+r0)*H_, ob1=((size_t)b*T_+r1)*H_;
#pragma unroll
            for(int f=0;f<8;f++){
                int h=f*8+(lane&3)*2;
                *(float2*)(out+ob0+h)=make_float2(o[mf][f][0]*i0,o[mf][f][1]*i0);
                *(float2*)(out+ob1+h)=make_float2(o[mf][f][2]*i1,o[mf][f][3]*i1);
            }
        }
    } else {
        float* pp=g_pacc+(size_t)id*8192;
#pragma unroll
        for(int mf=0;mf<2;mf++){
            int rl0=w*32+mf*16+(lane>>2), rl1=rl0+8;
#pragma unroll
            for(int f=0;f<8;f++){
                int h=f*8+(lane&3)*2;
                *(float2*)(pp+rl0*64+h)=make_float2(o[mf][f][0],o[mf][f][1]);
                *(float2*)(pp+rl1*64+h)=make_float2(o[mf][f][2],o[mf][f][3]);
            }
            if((lane&3)==0){
                g_pm[id*128+rl0]=m[mf][0]; g_pl[id*128+rl0]=l[mf][0];
                g_pm[id*128+rl1]=m[mf][1]; g_pl[id*128+rl1]=l[mf][1];
            }
        }
    }
}

// ------------- Kernel 3: combine partials — 384 CTAs, batched loads ---------
__global__ void __launch_bounds__(128)
comb_kernel(float* __restrict__ out){
    const int qq=(blockIdx.x>>2)+8, rg=blockIdx.x&3, b=blockIdx.y;
    const int g=qq>>3, rr=qq&7;
    const int base=b*IPB+(g+1)*(4*g+rr), nseg=g+1;
    const int ql=rg*32+(threadIdx.x>>2), hg=(threadIdx.x&3)*16;

    // batched m/l loads
    float pm[4], pl[4];
#pragma unroll
    for(int s=0;s<4;s++){
        if(s<nseg){ pm[s]=g_pm[(base+s)*128+ql]; pl[s]=g_pl[(base+s)*128+ql]; }
        else      { pm[s]=-INFINITY; pl[s]=0.f; }
    }
    // batched partial-O loads: up to 16 float4 in flight
    float4 dat[4][4];
#pragma unroll
    for(int s=0;s<4;s++){
        if(s<nseg){
            const float4* p=(const float4*)(g_pacc+((size_t)(base+s)*8192+ql*64+hg));
#pragma unroll
            for(int i=0;i<4;i++) dat[s][i]=p[i];
        }
    }
    float mstar=fmaxf(fmaxf(pm[0],pm[1]),fmaxf(pm[2],pm[3]));
    float wgt[4], lsum=0.f;
#pragma unroll
    for(int s=0;s<4;s++){
        wgt[s]=__expf(pm[s]-mstar);
        lsum+=pl[s]*wgt[s];
    }
    float acc[16];
#pragma unroll
    for(int i=0;i<16;i++) acc[i]=0.f;
#pragma unroll
    for(int s=0;s<4;s++){
        if(s<nseg){
            float wg=wgt[s];
#pragma unroll
            for(int i=0;i<4;i++){
                acc[4*i]  +=wg*dat[s][i].x; acc[4*i+1]+=wg*dat[s][i].y;
                acc[4*i+2]+=wg*dat[s][i].z; acc[4*i+3]+=wg*dat[s][i].w;
            }
        }
    }
    float inv=1.f/lsum;
    float4* po=(float4*)(out+((size_t)b*T_+qq*128+ql)*H_+hg);
#pragma unroll
    for(int i=0;i<4;i++)
        po[i]=make_float4(acc[4*i]*inv,acc[4*i+1]*inv,acc[4*i+2]*inv,acc[4*i+3]*inv);
}

extern "C" void kernel_launch(void* const* d_in, const int* in_sizes, int n_in,
                              void* d_out, int out_size){
    prep_w<<<128,128>>>((const float*)d_in[1],(const float*)d_in[2],(const float*)d_in[3]);
    qkv_kernel<<<(B_*T_)/128,512>>>((const float*)d_in[0]);
    attn_kernel<<<NIT,128>>>((float*)d_out);
    comb_kernel<<<dim3(96,4),128>>>((float*)d_out);
}

// round 16
// speedup vs baseline: 1.0462x; 1.0227x over previous
#include <cuda_runtime.h>
#include <cuda_fp16.h>
#include <math.h>
#include <stdint.h>

#define B_ 4
#define T_ 4096
#define C_ 1024
#define H_ 64
#define IPB 80                       // sum over 32 qtiles of (qq/8+1)
#define NIT (B_*IPB)                 // 320

__device__ __half g_q[B_*T_*H_];     // [b][t][h], 1/32 folded
__device__ __half g_k[B_*T_*H_];
__device__ __half g_v[B_*H_*T_];     // transposed [b][h][t]
__device__ __half g_w[C_*192];       // fp16 W in [k][n] (q|k|v), 1/32 folded in q
__device__ __half g_pacc[(size_t)NIT*128*64];   // fp16 partial O
__device__ float g_pm[NIT*128], g_pl[NIT*128];

__device__ __forceinline__ uint32_t su32(const void* p){ return (uint32_t)__cvta_generic_to_shared(p); }
__device__ __forceinline__ void ldsm4(uint32_t a, uint32_t& r0, uint32_t& r1, uint32_t& r2, uint32_t& r3){
    asm volatile("ldmatrix.sync.aligned.m8n8.x4.shared.b16 {%0,%1,%2,%3}, [%4];"
                 : "=r"(r0),"=r"(r1),"=r"(r2),"=r"(r3) : "r"(a));
}
__device__ __forceinline__ void ldsm4t(uint32_t a, uint32_t& r0, uint32_t& r1, uint32_t& r2, uint32_t& r3){
    asm volatile("ldmatrix.sync.aligned.m8n8.x4.trans.shared.b16 {%0,%1,%2,%3}, [%4];"
                 : "=r"(r0),"=r"(r1),"=r"(r2),"=r"(r3) : "r"(a));
}
__device__ __forceinline__ void mmaf16(float* d, const uint32_t* a, uint32_t b0, uint32_t b1){
    asm volatile("mma.sync.aligned.m16n8k16.row.col.f32.f16.f16.f32 "
                 "{%0,%1,%2,%3}, {%4,%5,%6,%7}, {%8,%9}, {%0,%1,%2,%3};"
                 : "+f"(d[0]),"+f"(d[1]),"+f"(d[2]),"+f"(d[3])
                 : "r"(a[0]),"r"(a[1]),"r"(a[2]),"r"(a[3]),"r"(b0),"r"(b1));
}
__device__ __forceinline__ uint32_t packh2(float x, float y){
    __half2 h = __float22half2_rn(make_float2(x,y));
    return *(uint32_t*)&h;
}
__device__ __forceinline__ void cpa16(uint32_t dst, const void* src){
    asm volatile("cp.async.cg.shared.global [%0], [%1], 16;"::"r"(dst),"l"(src));
}
__device__ __forceinline__ void cpcommit(){ asm volatile("cp.async.commit_group;"); }
template<int N> __device__ __forceinline__ void cpwait(){
    asm volatile("cp.async.wait_group %0;"::"n"(N));
}

// ------------- Kernel 0: streaming convert W fp32->fp16, [k][n] layout ------
__global__ void __launch_bounds__(128)
prep_w(const float* __restrict__ Wq, const float* __restrict__ Wk,
       const float* __restrict__ Wv){
    const int t=blockIdx.x*128+threadIdx.x;
    const int k=t>>4, h4=(t&15)<<2;
    float4 q =*(const float4*)(Wq+(size_t)k*H_+h4);
    float4 kk=*(const float4*)(Wk+(size_t)k*H_+h4);
    float4 vv=*(const float4*)(Wv+(size_t)k*H_+h4);
    __half* d=g_w+(size_t)k*192;
    *(uint2*)(d+h4)    =make_uint2(packh2(q.x*0.03125f,q.y*0.03125f),
                                   packh2(q.z*0.03125f,q.w*0.03125f));
    *(uint2*)(d+64+h4) =make_uint2(packh2(kk.x,kk.y),packh2(kk.z,kk.w));
    *(uint2*)(d+128+h4)=make_uint2(packh2(vv.x,vv.y),packh2(vv.z,vv.w));
}

// ------------- Kernel 1: fused QKV, M=128, 512 thr, W via cp.async ----------
#define XS 40
#define XTS (128*XS)
#define XSW 200
#define WTS (32*XSW)
__global__ void __launch_bounds__(512,1)
qkv_kernel(const float* __restrict__ x){
    __shared__ __half xs[2][XTS], ws[2][WTS];
    const int tid=threadIdx.x, lane=tid&31, w=tid>>5;
    const int wm=w>>2, wn=w&3;
    const int row0=blockIdx.x*128;

    float acc[2][6][4];
#pragma unroll
    for(int a=0;a<2;a++)
#pragma unroll
        for(int b=0;b<6;b++)
#pragma unroll
            for(int i=0;i<4;i++) acc[a][b][i]=0.f;

    const int ra_=(lane&15), ca_=(lane>>4)*8;
    const int rbt=((lane>>3)&1)*8+(lane&7), cbt=(lane>>4)*8;
    const int xr0=tid>>3, xc0=(tid&7)<<2;
    const int wi0=tid, wi1=512+(tid&255);
    const int wr0=wi0/24, wc0=(wi0%24)<<3;
    const int wr1=wi1/24, wc1=(wi1%24)<<3;
    const bool wdo1=(tid<256);

    float4 xv[2];
    xv[0]=*(const float4*)(x+(size_t)(row0+xr0)*C_+xc0);
    xv[1]=*(const float4*)(x+(size_t)(row0+xr0+64)*C_+xc0);
    cpa16(su32(&ws[0][wr0*XSW+wc0]), g_w+(size_t)wr0*192+wc0);
    if(wdo1) cpa16(su32(&ws[0][wr1*XSW+wc1]), g_w+(size_t)wr1*192+wc1);
    cpcommit();

    for(int k0=0, it=0; k0<C_; k0+=32, it++){
        const int cur=it&1;
        const bool more=(k0+32<C_);
        if(more){
            cpa16(su32(&ws[cur^1][wr0*XSW+wc0]), g_w+(size_t)(k0+32+wr0)*192+wc0);
            if(wdo1) cpa16(su32(&ws[cur^1][wr1*XSW+wc1]), g_w+(size_t)(k0+32+wr1)*192+wc1);
            cpcommit();
        }
#pragma unroll
        for(int i=0;i<2;i++){
            int r=xr0+i*64;
            *(uint2*)&xs[cur][r*XS+xc0]=make_uint2(packh2(xv[i].x,xv[i].y),
                                                   packh2(xv[i].z,xv[i].w));
        }
        if(more){
            xv[0]=*(const float4*)(x+(size_t)(row0+xr0)*C_+k0+32+xc0);
            xv[1]=*(const float4*)(x+(size_t)(row0+xr0+64)*C_+k0+32+xc0);
        }
        if(more) cpwait<1>(); else cpwait<0>();
        __syncthreads();

#pragma unroll
        for(int ks=0;ks<32;ks+=16){
            uint32_t a[2][4];
#pragma unroll
            for(int mf=0;mf<2;mf++){
                int rr=wm*32+mf*16+ra_, cc=ks+ca_;
                ldsm4(su32(&xs[cur][rr*XS+cc]),a[mf][0],a[mf][1],a[mf][2],a[mf][3]);
            }
#pragma unroll
            for(int p=0;p<3;p++){
                int n0=wn*48+p*16;
                uint32_t b[4];
                ldsm4t(su32(&ws[cur][(ks+rbt)*XSW+n0+cbt]),b[0],b[1],b[2],b[3]);
#pragma unroll
                for(int mf=0;mf<2;mf++){
                    mmaf16(acc[mf][p*2],  a[mf],b[0],b[1]);
                    mmaf16(acc[mf][p*2+1],a[mf],b[2],b[3]);
                }
            }
        }
        __syncthreads();
    }
#pragma unroll
    for(int mf=0;mf<2;mf++){
        int r0=row0+wm*32+mf*16+(lane>>2), r1=r0+8;
#pragma unroll
        for(int nf=0;nf<6;nf++){
            int n=wn*48+nf*8+(lane&3)*2, mat=n>>6, h=n&63;
            float* d=acc[mf][nf];
            if(mat<2){
                __half* dst = mat? g_k : g_q;
                *(uint32_t*)(dst+(size_t)r0*H_+h)=packh2(d[0],d[1]);
                *(uint32_t*)(dst+(size_t)r1*H_+h)=packh2(d[2],d[3]);
            } else {
                int b0=r0>>12, t0=r0&4095, b1=r1>>12, t1=r1&4095;
                size_t o0=((size_t)b0*H_+h)*T_+t0, o1=((size_t)b1*H_+h)*T_+t1;
                g_v[o0]=__float2half(d[0]); g_v[o0+T_]=__float2half(d[1]);
                g_v[o1]=__float2half(d[2]); g_v[o1+T_]=__float2half(d[3]);
            }
        }
    }
}

// ------------- Kernel 2: fp16 flash attention (seg=16, fp16 partials) -------
#define KS 72
#define STG (64*KS)
__global__ void __launch_bounds__(128)
attn_kernel(float* __restrict__ out){
    __shared__ __half ks[2][STG], vs[2][STG];
    const int tid=threadIdx.x, lane=tid&31, w=tid>>5;
    int id=(int)gridDim.x-1-blockIdx.x;              // heavy first
    int b=id/IPB, r=id%IPB, qq=0;
    for(;;){ int c=(qq>>3)+1; if(r<c) break; r-=c; qq++; }
    const int seg=r, nsegs=(qq>>3)+1;
    const int j0=seg*16, j1=min(j0+16, 2*qq+2);
    const int qrb=qq*128 + w*32 + (lane>>2);

    const __half *qp=g_q+(size_t)b*T_*H_;
    const __half *kp=g_k+(size_t)b*T_*H_;
    const __half *vp=g_v+(size_t)b*H_*T_;
    const int lr=tid>>3, lc=(tid&7)<<3;

#pragma unroll
    for(int i=0;i<4;i++){
        int rr=lr+i*16;
        cpa16(su32(&ks[0][rr*KS+lc]), kp+(size_t)(j0*64+rr)*H_+lc);
        cpa16(su32(&vs[0][rr*KS+lc]), vp+(size_t)rr*T_+j0*64+lc);
    }
    cpcommit();

    uint32_t qa[2][4][4];
#pragma unroll
    for(int mf=0;mf<2;mf++)
#pragma unroll
        for(int s=0;s<4;s++){
            int c0=s*16+(lane&3)*2;
            size_t o0=(size_t)(qrb+mf*16)*H_, o1=(size_t)(qrb+mf*16+8)*H_;
            qa[mf][s][0]=*(const uint32_t*)(qp+o0+c0);
            qa[mf][s][1]=*(const uint32_t*)(qp+o1+c0);
            qa[mf][s][2]=*(const uint32_t*)(qp+o0+c0+8);
            qa[mf][s][3]=*(const uint32_t*)(qp+o1+c0+8);
        }

    float o[2][8][4];
#pragma unroll
    for(int mf=0;mf<2;mf++)
#pragma unroll
        for(int f=0;f<8;f++){o[mf][f][0]=0.f;o[mf][f][1]=0.f;o[mf][f][2]=0.f;o[mf][f][3]=0.f;}
    float m[2][2], l[2][2];
#pragma unroll
    for(int mf=0;mf<2;mf++){m[mf][0]=-INFINITY;m[mf][1]=-INFINITY;l[mf][0]=0.f;l[mf][1]=0.f;}
    const int rb=(lane>>4)*8+(lane&7), cb=((lane>>3)&1)*8;

    for(int j=j0;j<j1;j++){
        const int cur=(j-j0)&1;
        if(j+1<j1){
            const int nx=cur^1;
#pragma unroll
            for(int i=0;i<4;i++){
                int rr=lr+i*16;
                cpa16(su32(&ks[nx][rr*KS+lc]), kp+(size_t)((j+1)*64+rr)*H_+lc);
                cpa16(su32(&vs[nx][rr*KS+lc]), vp+(size_t)rr*T_+(j+1)*64+lc);
            }
            cpcommit(); cpwait<1>();
        } else cpwait<0>();
        __syncthreads();

        float sa[2][8][4];
#pragma unroll
        for(int mf=0;mf<2;mf++)
#pragma unroll
            for(int f=0;f<8;f++){sa[mf][f][0]=0.f;sa[mf][f][1]=0.f;sa[mf][f][2]=0.f;sa[mf][f][3]=0.f;}
#pragma unroll
        for(int s=0;s<4;s++)
#pragma unroll
            for(int p=0;p<4;p++){
                uint32_t bb[4];
                ldsm4(su32(&ks[cur][(p*16+rb)*KS+s*16+cb]),bb[0],bb[1],bb[2],bb[3]);
#pragma unroll
                for(int mf=0;mf<2;mf++){
                    mmaf16(sa[mf][p*2],  qa[mf][s],bb[0],bb[1]);
                    mmaf16(sa[mf][p*2+1],qa[mf][s],bb[2],bb[3]);
                }
            }

        if(j>=2*qq){
#pragma unroll
            for(int mf=0;mf<2;mf++){
                int q0=qrb+mf*16, q1=q0+8;
#pragma unroll
                for(int f=0;f<8;f++){
                    int kg=j*64+f*8+(lane&3)*2;
                    if(kg  >q0) sa[mf][f][0]=-INFINITY;
                    if(kg+1>q0) sa[mf][f][1]=-INFINITY;
                    if(kg  >q1) sa[mf][f][2]=-INFINITY;
                    if(kg+1>q1) sa[mf][f][3]=-INFINITY;
                }
            }
        }

        uint32_t ph[2][4][4];
#pragma unroll
        for(int mf=0;mf<2;mf++){
            float mt0=-INFINITY,mt1=-INFINITY;
#pragma unroll
            for(int f=0;f<8;f++){
                mt0=fmaxf(mt0,fmaxf(sa[mf][f][0],sa[mf][f][1]));
                mt1=fmaxf(mt1,fmaxf(sa[mf][f][2],sa[mf][f][3]));
            }
            mt0=fmaxf(mt0,__shfl_xor_sync(~0u,mt0,1)); mt0=fmaxf(mt0,__shfl_xor_sync(~0u,mt0,2));
            mt1=fmaxf(mt1,__shfl_xor_sync(~0u,mt1,1)); mt1=fmaxf(mt1,__shfl_xor_sync(~0u,mt1,2));
            float mn0=fmaxf(m[mf][0],mt0), mn1=fmaxf(m[mf][1],mt1);
            float a0=__expf(m[mf][0]-mn0), a1=__expf(m[mf][1]-mn1);
            float s0=0.f,s1=0.f;
#pragma unroll
            for(int f=0;f<8;f++){
                sa[mf][f][0]=__expf(sa[mf][f][0]-mn0); s0+=sa[mf][f][0];
                sa[mf][f][1]=__expf(sa[mf][f][1]-mn0); s0+=sa[mf][f][1];
                sa[mf][f][2]=__expf(sa[mf][f][2]-mn1); s1+=sa[mf][f][2];
                sa[mf][f][3]=__expf(sa[mf][f][3]-mn1); s1+=sa[mf][f][3];
            }
            s0+=__shfl_xor_sync(~0u,s0,1); s0+=__shfl_xor_sync(~0u,s0,2);
            s1+=__shfl_xor_sync(~0u,s1,1); s1+=__shfl_xor_sync(~0u,s1,2);
            l[mf][0]=l[mf][0]*a0+s0; l[mf][1]=l[mf][1]*a1+s1;
            m[mf][0]=mn0; m[mf][1]=mn1;
#pragma unroll
            for(int f=0;f<8;f++){
                o[mf][f][0]*=a0; o[mf][f][1]*=a0; o[mf][f][2]*=a1; o[mf][f][3]*=a1;
            }
#pragma unroll
            for(int s=0;s<4;s++){
                ph[mf][s][0]=packh2(sa[mf][2*s][0],  sa[mf][2*s][1]);
                ph[mf][s][1]=packh2(sa[mf][2*s][2],  sa[mf][2*s][3]);
                ph[mf][s][2]=packh2(sa[mf][2*s+1][0],sa[mf][2*s+1][1]);
                ph[mf][s][3]=packh2(sa[mf][2*s+1][2],sa[mf][2*s+1][3]);
            }
        }

#pragma unroll
        for(int s=0;s<4;s++)
#pragma unroll
            for(int p=0;p<4;p++){
                uint32_t bb[4];
                ldsm4(su32(&vs[cur][(p*16+rb)*KS+s*16+cb]),bb[0],bb[1],bb[2],bb[3]);
#pragma unroll
                for(int mf=0;mf<2;mf++){
                    mmaf16(o[mf][p*2],  ph[mf][s],bb[0],bb[1]);
                    mmaf16(o[mf][p*2+1],ph[mf][s],bb[2],bb[3]);
                }
            }
        __syncthreads();
    }

    if(nsegs==1){
#pragma unroll
        for(int mf=0;mf<2;mf++){
            int r0=qrb+mf*16, r1=r0+8;
            float i0=1.f/l[mf][0], i1=1.f/l[mf][1];
            size_t ob0=((size_t)b*T_+r0)*H_, ob1=((size_t)b*T_+r1)*H_;
#pragma unroll
            for(int f=0;f<8;f++){
                int h=f*8+(lane&3)*2;
                *(float2*)(out+ob0+h)=make_float2(o[mf][f][0]*i0,o[mf][f][1]*i0);
                *(float2*)(out+ob1+h)=make_float2(o[mf][f][2]*i1,o[mf][f][3]*i1);
            }
        }
    } else {
        __half* pp=g_pacc+(size_t)id*8192;
#pragma unroll
        for(int mf=0;mf<2;mf++){
            int rl0=w*32+mf*16+(lane>>2), rl1=rl0+8;
#pragma unroll
            for(int f=0;f<8;f++){
                int h=f*8+(lane&3)*2;
                *(uint32_t*)(pp+rl0*64+h)=packh2(o[mf][f][0],o[mf][f][1]);
                *(uint32_t*)(pp+rl1*64+h)=packh2(o[mf][f][2],o[mf][f][3]);
            }
            if((lane&3)==0){
                g_pm[id*128+rl0]=m[mf][0]; g_pl[id*128+rl0]=l[mf][0];
                g_pm[id*128+rl1]=m[mf][1]; g_pl[id*128+rl1]=l[mf][1];
            }
        }
    }
}

// ------------- Kernel 3: combine fp16 partials — 384 CTAs, batched ----------
__global__ void __launch_bounds__(128)
comb_kernel(float* __restrict__ out){
    const int qq=(blockIdx.x>>2)+8, rg=blockIdx.x&3, b=blockIdx.y;
    const int g=qq>>3, rr=qq&7;
    const int base=b*IPB+(g+1)*(4*g+rr), nseg=g+1;
    const int ql=rg*32+(threadIdx.x>>2), hg=(threadIdx.x&3)*16;

    float pm[4], pl[4];
#pragma unroll
    for(int s=0;s<4;s++){
        if(s<nseg){ pm[s]=g_pm[(base+s)*128+ql]; pl[s]=g_pl[(base+s)*128+ql]; }
        else      { pm[s]=-INFINITY; pl[s]=0.f; }
    }
    // batched fp16 partial-O loads: up to 8 uint4 (16B) in flight
    uint4 dat[4][2];
#pragma unroll
    for(int s=0;s<4;s++){
        if(s<nseg){
            const uint4* p=(const uint4*)(g_pacc+((size_t)(base+s)*8192+ql*64+hg));
            dat[s][0]=p[0]; dat[s][1]=p[1];
        }
    }
    float mstar=fmaxf(fmaxf(pm[0],pm[1]),fmaxf(pm[2],pm[3]));
    float wgt[4], lsum=0.f;
#pragma unroll
    for(int s=0;s<4;s++){
        wgt[s]=__expf(pm[s]-mstar);
        lsum+=pl[s]*wgt[s];
    }
    float acc[16];
#pragma unroll
    for(int i=0;i<16;i++) acc[i]=0.f;
#pragma unroll
    for(int s=0;s<4;s++){
        if(s<nseg){
            float wg=wgt[s];
#pragma unroll
            for(int h=0;h<2;h++){
                const uint32_t* u=(const uint32_t*)&dat[s][h];
#pragma unroll
                for(int i=0;i<4;i++){
                    float2 v=__half22float2(*(const __half2*)&u[i]);
                    acc[h*8+2*i]  +=wg*v.x;
                    acc[h*8+2*i+1]+=wg*v.y;
                }
            }
        }
    }
    float inv=1.f/lsum;
    float4* po=(float4*)(out+((size_t)b*T_+qq*128+ql)*H_+hg);
#pragma unroll
    for(int i=0;i<4;i++)
        po[i]=make_float4(acc[4*i]*inv,acc[4*i+1]*inv,acc[4*i+2]*inv,acc[4*i+3]*inv);
}

extern "C" void kernel_launch(void* const* d_in, const int* in_sizes, int n_in,
                              void* d_out, int out_size){
    prep_w<<<128,128>>>((const float*)d_in[1],(const float*)d_in[2],(const float*)d_in[3]);
    qkv_kernel<<<(B_*T_)/128,512>>>((const float*)d_in[0]);
    attn_kernel<<<NIT,128>>>((float*)d_out);
    comb_kernel<<<dim3(96,4),128>>>((float*)d_out);
}

// round 17
// speedup vs baseline: 1.0488x; 1.0025x over previous
#include <cuda_runtime.h>
#include <cuda_fp16.h>
#include <math.h>
#include <stdint.h>

#define B_ 4
#define T_ 4096
#define C_ 1024
#define H_ 64
#define IPB 80                       // sum over 32 qtiles of (qq/8+1)
#define NIT (B_*IPB)                 // 320

__device__ __half g_q[B_*T_*H_];     // [b][t][h], 1/32 folded
__device__ __half g_k[B_*T_*H_];
__device__ __half g_v[B_*H_*T_];     // transposed [b][h][t]
__device__ __half g_w[C_*192];       // fp16 W in [k][n] (q|k|v), 1/32 folded in q
__device__ __half g_pacc[(size_t)NIT*128*64];   // fp16 partial O
__device__ float g_pm[NIT*128], g_pl[NIT*128];

__device__ __forceinline__ uint32_t su32(const void* p){ return (uint32_t)__cvta_generic_to_shared(p); }
__device__ __forceinline__ void ldsm4(uint32_t a, uint32_t& r0, uint32_t& r1, uint32_t& r2, uint32_t& r3){
    asm volatile("ldmatrix.sync.aligned.m8n8.x4.shared.b16 {%0,%1,%2,%3}, [%4];"
                 : "=r"(r0),"=r"(r1),"=r"(r2),"=r"(r3) : "r"(a));
}
__device__ __forceinline__ void ldsm4t(uint32_t a, uint32_t& r0, uint32_t& r1, uint32_t& r2, uint32_t& r3){
    asm volatile("ldmatrix.sync.aligned.m8n8.x4.trans.shared.b16 {%0,%1,%2,%3}, [%4];"
                 : "=r"(r0),"=r"(r1),"=r"(r2),"=r"(r3) : "r"(a));
}
__device__ __forceinline__ void mmaf16(float* d, const uint32_t* a, uint32_t b0, uint32_t b1){
    asm volatile("mma.sync.aligned.m16n8k16.row.col.f32.f16.f16.f32 "
                 "{%0,%1,%2,%3}, {%4,%5,%6,%7}, {%8,%9}, {%0,%1,%2,%3};"
                 : "+f"(d[0]),"+f"(d[1]),"+f"(d[2]),"+f"(d[3])
                 : "r"(a[0]),"r"(a[1]),"r"(a[2]),"r"(a[3]),"r"(b0),"r"(b1));
}
__device__ __forceinline__ uint32_t packh2(float x, float y){
    __half2 h = __float22half2_rn(make_float2(x,y));
    return *(uint32_t*)&h;
}
__device__ __forceinline__ void cpa16(uint32_t dst, const void* src){
    asm volatile("cp.async.cg.shared.global [%0], [%1], 16;"::"r"(dst),"l"(src));
}
__device__ __forceinline__ void cpcommit(){ asm volatile("cp.async.commit_group;"); }
template<int N> __device__ __forceinline__ void cpwait(){
    asm volatile("cp.async.wait_group %0;"::"n"(N));
}

// ------------- Kernel 0: streaming convert W fp32->fp16, [k][n] layout ------
__global__ void __launch_bounds__(128)
prep_w(const float* __restrict__ Wq, const float* __restrict__ Wk,
       const float* __restrict__ Wv){
    const int t=blockIdx.x*128+threadIdx.x;
    const int k=t>>4, h4=(t&15)<<2;
    float4 q =*(const float4*)(Wq+(size_t)k*H_+h4);
    float4 kk=*(const float4*)(Wk+(size_t)k*H_+h4);
    float4 vv=*(const float4*)(Wv+(size_t)k*H_+h4);
    __half* d=g_w+(size_t)k*192;
    *(uint2*)(d+h4)    =make_uint2(packh2(q.x*0.03125f,q.y*0.03125f),
                                   packh2(q.z*0.03125f,q.w*0.03125f));
    *(uint2*)(d+64+h4) =make_uint2(packh2(kk.x,kk.y),packh2(kk.z,kk.w));
    *(uint2*)(d+128+h4)=make_uint2(packh2(vv.x,vv.y),packh2(vv.z,vv.w));
}

// ------------- Kernel 1: fused QKV, M=128, 512 thr, V staged via smem -------
#define XS 40
#define XTS (128*XS)
#define XSW 200
#define WTS (32*XSW)
__global__ void __launch_bounds__(512,1)
qkv_kernel(const float* __restrict__ x){
    __shared__ __half xs[2][XTS], ws[2][WTS];
    const int tid=threadIdx.x, lane=tid&31, w=tid>>5;
    const int wm=w>>2, wn=w&3;
    const int row0=blockIdx.x*128;

    float acc[2][6][4];
#pragma unroll
    for(int a=0;a<2;a++)
#pragma unroll
        for(int b=0;b<6;b++)
#pragma unroll
            for(int i=0;i<4;i++) acc[a][b][i]=0.f;

    const int ra_=(lane&15), ca_=(lane>>4)*8;
    const int rbt=((lane>>3)&1)*8+(lane&7), cbt=(lane>>4)*8;
    const int xr0=tid>>3, xc0=(tid&7)<<2;
    const int wi0=tid, wi1=512+(tid&255);
    const int wr0=wi0/24, wc0=(wi0%24)<<3;
    const int wr1=wi1/24, wc1=(wi1%24)<<3;
    const bool wdo1=(tid<256);

    float4 xv[2];
    xv[0]=*(const float4*)(x+(size_t)(row0+xr0)*C_+xc0);
    xv[1]=*(const float4*)(x+(size_t)(row0+xr0+64)*C_+xc0);
    cpa16(su32(&ws[0][wr0*XSW+wc0]), g_w+(size_t)wr0*192+wc0);
    if(wdo1) cpa16(su32(&ws[0][wr1*XSW+wc1]), g_w+(size_t)wr1*192+wc1);
    cpcommit();

    for(int k0=0, it=0; k0<C_; k0+=32, it++){
        const int cur=it&1;
        const bool more=(k0+32<C_);
        if(more){
            cpa16(su32(&ws[cur^1][wr0*XSW+wc0]), g_w+(size_t)(k0+32+wr0)*192+wc0);
            if(wdo1) cpa16(su32(&ws[cur^1][wr1*XSW+wc1]), g_w+(size_t)(k0+32+wr1)*192+wc1);
            cpcommit();
        }
#pragma unroll
        for(int i=0;i<2;i++){
            int r=xr0+i*64;
            *(uint2*)&xs[cur][r*XS+xc0]=make_uint2(packh2(xv[i].x,xv[i].y),
                                                   packh2(xv[i].z,xv[i].w));
        }
        if(more){
            xv[0]=*(const float4*)(x+(size_t)(row0+xr0)*C_+k0+32+xc0);
            xv[1]=*(const float4*)(x+(size_t)(row0+xr0+64)*C_+k0+32+xc0);
        }
        if(more) cpwait<1>(); else cpwait<0>();
        __syncthreads();

#pragma unroll
        for(int ks=0;ks<32;ks+=16){
            uint32_t a[2][4];
#pragma unroll
            for(int mf=0;mf<2;mf++){
                int rr=wm*32+mf*16+ra_, cc=ks+ca_;
                ldsm4(su32(&xs[cur][rr*XS+cc]),a[mf][0],a[mf][1],a[mf][2],a[mf][3]);
            }
#pragma unroll
            for(int p=0;p<3;p++){
                int n0=wn*48+p*16;
                uint32_t b[4];
                ldsm4t(su32(&ws[cur][(ks+rbt)*XSW+n0+cbt]),b[0],b[1],b[2],b[3]);
#pragma unroll
                for(int mf=0;mf<2;mf++){
                    mmaf16(acc[mf][p*2],  a[mf],b[0],b[1]);
                    mmaf16(acc[mf][p*2+1],a[mf],b[2],b[3]);
                }
            }
        }
        __syncthreads();
    }

    // epilogue: Q/K direct; V staged into smem [h][t] (stride 136) then coalesced
    __half* vsm=&xs[0][0];                       // 64*136 halfs = 17408 B <= 20480 B
#pragma unroll
    for(int mf=0;mf<2;mf++){
        int r0=row0+wm*32+mf*16+(lane>>2), r1=r0+8;
        int tl0=r0-row0, tl1=r1-row0;
#pragma unroll
        for(int nf=0;nf<6;nf++){
            int n=wn*48+nf*8+(lane&3)*2, mat=n>>6, h=n&63;
            float* d=acc[mf][nf];
            if(mat<2){
                __half* dst = mat? g_k : g_q;
                *(uint32_t*)(dst+(size_t)r0*H_+h)=packh2(d[0],d[1]);
                *(uint32_t*)(dst+(size_t)r1*H_+h)=packh2(d[2],d[3]);
            } else {
                vsm[h*136+tl0]    =__float2half(d[0]);
                vsm[(h+1)*136+tl0]=__float2half(d[1]);
                vsm[h*136+tl1]    =__float2half(d[2]);
                vsm[(h+1)*136+tl1]=__float2half(d[3]);
            }
        }
    }
    __syncthreads();
    {
        const int bb=row0>>12, t0b=row0&4095;
#pragma unroll
        for(int i=0;i<2;i++){
            int idx=tid+i*512;
            int h=idx>>4, tl=(idx&15)<<3;
            *(uint4*)(g_v+((size_t)bb*H_+h)*T_+t0b+tl)=*(uint4*)(vsm+h*136+tl);
        }
    }
}

// ------------- Kernel 2: fp16 flash attention (seg=16, fp16 partials) -------
#define KS 72
#define STG (64*KS)
__global__ void __launch_bounds__(128)
attn_kernel(float* __restrict__ out){
    __shared__ __half ks[2][STG], vs[2][STG];
    const int tid=threadIdx.x, lane=tid&31, w=tid>>5;
    int id=(int)gridDim.x-1-blockIdx.x;              // heavy first
    int b=id/IPB, r=id%IPB, qq=0;
    for(;;){ int c=(qq>>3)+1; if(r<c) break; r-=c; qq++; }
    const int seg=r, nsegs=(qq>>3)+1;
    const int j0=seg*16, j1=min(j0+16, 2*qq+2);
    const int qrb=qq*128 + w*32 + (lane>>2);

    const __half *qp=g_q+(size_t)b*T_*H_;
    const __half *kp=g_k+(size_t)b*T_*H_;
    const __half *vp=g_v+(size_t)b*H_*T_;
    const int lr=tid>>3, lc=(tid&7)<<3;

#pragma unroll
    for(int i=0;i<4;i++){
        int rr=lr+i*16;
        cpa16(su32(&ks[0][rr*KS+lc]), kp+(size_t)(j0*64+rr)*H_+lc);
        cpa16(su32(&vs[0][rr*KS+lc]), vp+(size_t)rr*T_+j0*64+lc);
    }
    cpcommit();

    uint32_t qa[2][4][4];
#pragma unroll
    for(int mf=0;mf<2;mf++)
#pragma unroll
        for(int s=0;s<4;s++){
            int c0=s*16+(lane&3)*2;
            size_t o0=(size_t)(qrb+mf*16)*H_, o1=(size_t)(qrb+mf*16+8)*H_;
            qa[mf][s][0]=*(const uint32_t*)(qp+o0+c0);
            qa[mf][s][1]=*(const uint32_t*)(qp+o1+c0);
            qa[mf][s][2]=*(const uint32_t*)(qp+o0+c0+8);
            qa[mf][s][3]=*(const uint32_t*)(qp+o1+c0+8);
        }

    float o[2][8][4];
#pragma unroll
    for(int mf=0;mf<2;mf++)
#pragma unroll
        for(int f=0;f<8;f++){o[mf][f][0]=0.f;o[mf][f][1]=0.f;o[mf][f][2]=0.f;o[mf][f][3]=0.f;}
    float m[2][2], l[2][2];
#pragma unroll
    for(int mf=0;mf<2;mf++){m[mf][0]=-INFINITY;m[mf][1]=-INFINITY;l[mf][0]=0.f;l[mf][1]=0.f;}
    const int rb=(lane>>4)*8+(lane&7), cb=((lane>>3)&1)*8;

    for(int j=j0;j<j1;j++){
        const int cur=(j-j0)&1;
        if(j+1<j1){
            const int nx=cur^1;
#pragma unroll
            for(int i=0;i<4;i++){
                int rr=lr+i*16;
                cpa16(su32(&ks[nx][rr*KS+lc]), kp+(size_t)((j+1)*64+rr)*H_+lc);
                cpa16(su32(&vs[nx][rr*KS+lc]), vp+(size_t)rr*T_+(j+1)*64+lc);
            }
            cpcommit(); cpwait<1>();
        } else cpwait<0>();
        __syncthreads();

        float sa[2][8][4];
#pragma unroll
        for(int mf=0;mf<2;mf++)
#pragma unroll
            for(int f=0;f<8;f++){sa[mf][f][0]=0.f;sa[mf][f][1]=0.f;sa[mf][f][2]=0.f;sa[mf][f][3]=0.f;}
#pragma unroll
        for(int s=0;s<4;s++)
#pragma unroll
            for(int p=0;p<4;p++){
                uint32_t bb[4];
                ldsm4(su32(&ks[cur][(p*16+rb)*KS+s*16+cb]),bb[0],bb[1],bb[2],bb[3]);
#pragma unroll
                for(int mf=0;mf<2;mf++){
                    mmaf16(sa[mf][p*2],  qa[mf][s],bb[0],bb[1]);
                    mmaf16(sa[mf][p*2+1],qa[mf][s],bb[2],bb[3]);
                }
            }

        if(j>=2*qq){
#pragma unroll
            for(int mf=0;mf<2;mf++){
                int q0=qrb+mf*16, q1=q0+8;
#pragma unroll
                for(int f=0;f<8;f++){
                    int kg=j*64+f*8+(lane&3)*2;
                    if(kg  >q0) sa[mf][f][0]=-INFINITY;
                    if(kg+1>q0) sa[mf][f][1]=-INFINITY;
                    if(kg  >q1) sa[mf][f][2]=-INFINITY;
                    if(kg+1>q1) sa[mf][f][3]=-INFINITY;
                }
            }
        }

        uint32_t ph[2][4][4];
#pragma unroll
        for(int mf=0;mf<2;mf++){
            float mt0=-INFINITY,mt1=-INFINITY;
#pragma unroll
            for(int f=0;f<8;f++){
                mt0=fmaxf(mt0,fmaxf(sa[mf][f][0],sa[mf][f][1]));
                mt1=fmaxf(mt1,fmaxf(sa[mf][f][2],sa[mf][f][3]));
            }
            mt0=fmaxf(mt0,__shfl_xor_sync(~0u,mt0,1)); mt0=fmaxf(mt0,__shfl_xor_sync(~0u,mt0,2));
            mt1=fmaxf(mt1,__shfl_xor_sync(~0u,mt1,1)); mt1=fmaxf(mt1,__shfl_xor_sync(~0u,mt1,2));
            float mn0=fmaxf(m[mf][0],mt0), mn1=fmaxf(m[mf][1],mt1);
            float a0=__expf(m[mf][0]-mn0), a1=__expf(m[mf][1]-mn1);
            float s0=0.f,s1=0.f;
#pragma unroll
            for(int f=0;f<8;f++){
                sa[mf][f][0]=__expf(sa[mf][f][0]-mn0); s0+=sa[mf][f][0];
                sa[mf][f][1]=__expf(sa[mf][f][1]-mn0); s0+=sa[mf][f][1];
                sa[mf][f][2]=__expf(sa[mf][f][2]-mn1); s1+=sa[mf][f][2];
                sa[mf][f][3]=__expf(sa[mf][f][3]-mn1); s1+=sa[mf][f][3];
            }
            s0+=__shfl_xor_sync(~0u,s0,1); s0+=__shfl_xor_sync(~0u,s0,2);
            s1+=__shfl_xor_sync(~0u,s1,1); s1+=__shfl_xor_sync(~0u,s1,2);
            l[mf][0]=l[mf][0]*a0+s0; l[mf][1]=l[mf][1]*a1+s1;
            m[mf][0]=mn0; m[mf][1]=mn1;
#pragma unroll
            for(int f=0;f<8;f++){
                o[mf][f][0]*=a0; o[mf][f][1]*=a0; o[mf][f][2]*=a1; o[mf][f][3]*=a1;
            }
#pragma unroll
            for(int s=0;s<4;s++){
                ph[mf][s][0]=packh2(sa[mf][2*s][0],  sa[mf][2*s][1]);
                ph[mf][s][1]=packh2(sa[mf][2*s][2],  sa[mf][2*s][3]);
                ph[mf][s][2]=packh2(sa[mf][2*s+1][0],sa[mf][2*s+1][1]);
                ph[mf][s][3]=packh2(sa[mf][2*s+1][2],sa[mf][2*s+1][3]);
            }
        }

#pragma unroll
        for(int s=0;s<4;s++)
#pragma unroll
            for(int p=0;p<4;p++){
                uint32_t bb[4];
                ldsm4(su32(&vs[cur][(p*16+rb)*KS+s*16+cb]),bb[0],bb[1],bb[2],bb[3]);
#pragma unroll
                for(int mf=0;mf<2;mf++){
                    mmaf16(o[mf][p*2],  ph[mf][s],bb[0],bb[1]);
                    mmaf16(o[mf][p*2+1],ph[mf][s],bb[2],bb[3]);
                }
            }
        __syncthreads();
    }

    if(nsegs==1){
#pragma unroll
        for(int mf=0;mf<2;mf++){
            int r0=qrb+mf*16, r1=r0+8;
            float i0=1.f/l[mf][0], i1=1.f/l[mf][1];
            size_t ob0=((size_t)b*T_+r0)*H_, ob1=((size_t)b*T_+r1)*H_;
#pragma unroll
            for(int f=0;f<8;f++){
                int h=f*8+(lane&3)*2;
                *(float2*)(out+ob0+h)=make_float2(o[mf][f][0]*i0,o[mf][f][1]*i0);
                *(float2*)(out+ob1+h)=make_float2(o[mf][f][2]*i1,o[mf][f][3]*i1);
            }
        }
    } else {
        __half* pp=g_pacc+(size_t)id*8192;
#pragma unroll
        for(int mf=0;mf<2;mf++){
            int rl0=w*32+mf*16+(lane>>2), rl1=rl0+8;
#pragma unroll
            for(int f=0;f<8;f++){
                int h=f*8+(lane&3)*2;
                *(uint32_t*)(pp+rl0*64+h)=packh2(o[mf][f][0],o[mf][f][1]);
                *(uint32_t*)(pp+rl1*64+h)=packh2(o[mf][f][2],o[mf][f][3]);
            }
            if((lane&3)==0){
                g_pm[id*128+rl0]=m[mf][0]; g_pl[id*128+rl0]=l[mf][0];
                g_pm[id*128+rl1]=m[mf][1]; g_pl[id*128+rl1]=l[mf][1];
            }
        }
    }
}

// ------------- Kernel 3: combine fp16 partials — 384 CTAs, batched ----------
__global__ void __launch_bounds__(128)
comb_kernel(float* __restrict__ out){
    const int qq=(blockIdx.x>>2)+8, rg=blockIdx.x&3, b=blockIdx.y;
    const int g=qq>>3, rr=qq&7;
    const int base=b*IPB+(g+1)*(4*g+rr), nseg=g+1;
    const int ql=rg*32+(threadIdx.x>>2), hg=(threadIdx.x&3)*16;

    float pm[4], pl[4];
#pragma unroll
    for(int s=0;s<4;s++){
        if(s<nseg){ pm[s]=g_pm[(base+s)*128+ql]; pl[s]=g_pl[(base+s)*128+ql]; }
        else      { pm[s]=-INFINITY; pl[s]=0.f; }
    }
    uint4 dat[4][2];
#pragma unroll
    for(int s=0;s<4;s++){
        if(s<nseg){
            const uint4* p=(const uint4*)(g_pacc+((size_t)(base+s)*8192+ql*64+hg));
            dat[s][0]=p[0]; dat[s][1]=p[1];
        }
    }
    float mstar=fmaxf(fmaxf(pm[0],pm[1]),fmaxf(pm[2],pm[3]));
    float wgt[4], lsum=0.f;
#pragma unroll
    for(int s=0;s<4;s++){
        wgt[s]=__expf(pm[s]-mstar);
        lsum+=pl[s]*wgt[s];
    }
    float acc[16];
#pragma unroll
    for(int i=0;i<16;i++) acc[i]=0.f;
#pragma unroll
    for(int s=0;s<4;s++){
        if(s<nseg){
            float wg=wgt[s];
#pragma unroll
            for(int h=0;h<2;h++){
                const uint32_t* u=(const uint32_t*)&dat[s][h];
#pragma unroll
                for(int i=0;i<4;i++){
                    float2 v=__half22float2(*(const __half2*)&u[i]);
                    acc[h*8+2*i]  +=wg*v.x;
                    acc[h*8+2*i+1]+=wg*v.y;
                }
            }
        }
    }
    float inv=1.f/lsum;
    float4* po=(float4*)(out+((size_t)b*T_+qq*128+ql)*H_+hg);
#pragma unroll
    for(int i=0;i<4;i++)
        po[i]=make_float4(acc[4*i]*inv,acc[4*i+1]*inv,acc[4*i+2]*inv,acc[4*i+3]*inv);
}

extern "C" void kernel_launch(void* const* d_in, const int* in_sizes, int n_in,
                              void* d_out, int out_size){
    prep_w<<<128,128>>>((const float*)d_in[1],(const float*)d_in[2],(const float*)d_in[3]);
    qkv_kernel<<<(B_*T_)/128,512>>>((const float*)d_in[0]);
    attn_kernel<<<NIT,128>>>((float*)d_out);
    comb_kernel<<<dim3(96,4),128>>>((float*)d_out);
}